// round 1
// baseline (speedup 1.0000x reference)
#include <cuda_runtime.h>
#include <math.h>
#include <stdint.h>

// ============================================================================
// EventTransformer — fp32 SIMT baseline, ragged-sequence formulation.
//
// Reference semantics: padded tokens are masked out of attention and only the
// CLS row reaches the output, so padding can never affect the result. Since
// dom_to_event_idx is sorted, event b's tokens are contiguous:
//   token t of event b:  t==0 -> CLS, else dom (start[b] + t - 1)
//   flat token index of dom i = i + ev[i] + 1 ;  CLS of event b at start[b]+b
// Total tokens NT = N + B. Everything becomes flat [NT, *] GEMMs + a ragged
// flash-attention kernel per (event, head).
// ============================================================================

#define D_INP 128
#define DM    256
#define NH    4
#define HDIM  64
#define NL    4
#define DFF   1024
#define NMAXD 65536
#define BMAXD 128
#define NTMAX (NMAXD + BMAXD)

// ---- scratch (static device globals; runtime allocation is forbidden) ----
__device__ float g_tok[(size_t)NTMAX * DM];      // residual stream h
__device__ float g_buf[(size_t)NTMAX * DM];      // LN out / posenc / cls rows
__device__ float g_qkv[(size_t)NTMAX * 3 * DM];  // QKV
__device__ float g_att[(size_t)NTMAX * DM];      // attn out / dom embeds / head hid
__device__ float g_ff [(size_t)NTMAX * DFF];     // FF hidden
__device__ int   g_start[BMAXD + 1];

// ============================================================================
// starts[b] = lower_bound(ev, b)  (ev sorted);  starts[B] = N
// ============================================================================
__global__ void starts_kernel(const int* __restrict__ ev, int N, int B) {
    int b = blockIdx.x * blockDim.x + threadIdx.x;
    if (b > B) return;
    if (b == B) { g_start[B] = N; return; }
    int lo = 0, hi = N;
    while (lo < hi) {
        int mid = (lo + hi) >> 1;
        if (ev[mid] < b) lo = mid + 1; else hi = mid;
    }
    g_start[b] = lo;
}

// ============================================================================
// Positional encoding into g_buf[N, 256].
// enc col layout: axis d in 0..2, band j in 0..41, (sin, cos); cols 252..255 = 0
// freqs = 10^(j/41) computed as exp2f(j * log2(10)/41)
// ============================================================================
__global__ void posenc_kernel(const float* __restrict__ geom) {
    int i = blockIdx.x;
    int c = threadIdx.x;
    float val = 0.f;
    if (c < 252) {
        int dax  = c / 84;
        int rem  = c % 84;
        int band = rem >> 1;
        int s    = rem & 1;
        float f   = exp2f((float)band * 0.08102263646065820f); // log2(10)/41
        float ang = 6.283185307179586f * geom[i * 3 + dax] * f;
        val = s ? cosf(ang) : sinf(ang);
    }
    g_buf[(size_t)i * DM + c] = val;
}

// ============================================================================
// Generic GEMM: C[M,N] = (RES ? C : 0) + A[M,K] @ W[N,K]^T + bias[N], opt ReLU.
// 64x64 tile, BK=16, 256 threads, 4x4 micro-tile, smem stored k-major.
// ============================================================================
template<bool RELU, bool RES>
__global__ void gemm_kernel(const float* __restrict__ A, const float* __restrict__ W,
                            const float* __restrict__ bias, float* __restrict__ C,
                            int M, int N, int K) {
    __shared__ float As[16 * 64];
    __shared__ float Ws[16 * 64];
    int t  = threadIdx.x;
    int tx = t & 15, ty = t >> 4;
    int m0 = blockIdx.y * 64, n0 = blockIdx.x * 64;

    int lr = t >> 2;          // 0..63 (tile row)
    int lk = (t & 3) * 4;     // 0,4,8,12 (k sub-offset)
    const float* Arow = A + (size_t)(m0 + lr) * K + lk;
    const float* Wrow = W + (size_t)(n0 + lr) * K + lk;
    bool am = (m0 + lr) < M;
    bool wn = (n0 + lr) < N;

    float acc[4][4];
#pragma unroll
    for (int i = 0; i < 4; i++)
#pragma unroll
        for (int j = 0; j < 4; j++) acc[i][j] = 0.f;

    for (int k0 = 0; k0 < K; k0 += 16) {
        float4 a4 = am ? *(const float4*)(Arow + k0) : make_float4(0, 0, 0, 0);
        float4 w4 = wn ? *(const float4*)(Wrow + k0) : make_float4(0, 0, 0, 0);
        As[(lk + 0) * 64 + lr] = a4.x; As[(lk + 1) * 64 + lr] = a4.y;
        As[(lk + 2) * 64 + lr] = a4.z; As[(lk + 3) * 64 + lr] = a4.w;
        Ws[(lk + 0) * 64 + lr] = w4.x; Ws[(lk + 1) * 64 + lr] = w4.y;
        Ws[(lk + 2) * 64 + lr] = w4.z; Ws[(lk + 3) * 64 + lr] = w4.w;
        __syncthreads();
#pragma unroll
        for (int k = 0; k < 16; k++) {
            float4 av = *(const float4*)(As + k * 64 + ty * 4);
            float4 wv = *(const float4*)(Ws + k * 64 + tx * 4);
            acc[0][0] += av.x * wv.x; acc[0][1] += av.x * wv.y; acc[0][2] += av.x * wv.z; acc[0][3] += av.x * wv.w;
            acc[1][0] += av.y * wv.x; acc[1][1] += av.y * wv.y; acc[1][2] += av.y * wv.z; acc[1][3] += av.y * wv.w;
            acc[2][0] += av.z * wv.x; acc[2][1] += av.z * wv.y; acc[2][2] += av.z * wv.z; acc[2][3] += av.z * wv.w;
            acc[3][0] += av.w * wv.x; acc[3][1] += av.w * wv.y; acc[3][2] += av.w * wv.z; acc[3][3] += av.w * wv.w;
        }
        __syncthreads();
    }

#pragma unroll
    for (int i = 0; i < 4; i++) {
        int m = m0 + ty * 4 + i;
        if (m >= M) continue;
#pragma unroll
        for (int j = 0; j < 4; j++) {
            int n = n0 + tx * 4 + j;
            if (n >= N) continue;
            float v = acc[i][j] + bias[n];
            if (RES)  v += C[(size_t)m * N + n];
            if (RELU) v = fmaxf(v, 0.f);
            C[(size_t)m * N + n] = v;
        }
    }
}

// ============================================================================
// build token stream: g_tok[t] = CLS (if t == start[b]+b) else dom embed
// (dom embeds were written into g_att[0..N))
// ============================================================================
__global__ void build_tok(const float* __restrict__ cls, int B) {
    int tk = blockIdx.x;
    __shared__ int sb;
    if (threadIdx.x == 0) {
        int lo = 0, hi = B - 1;
        while (lo < hi) {
            int mid = (lo + hi + 1) >> 1;
            if (g_start[mid] + mid <= tk) lo = mid; else hi = mid - 1;
        }
        sb = lo;
    }
    __syncthreads();
    int b = sb;
    int d = threadIdx.x;
    float v;
    if (tk == g_start[b] + b) v = cls[d];
    else                      v = g_att[(size_t)(tk - b - 1) * DM + d];
    g_tok[(size_t)tk * DM + d] = v;
}

// ============================================================================
// LayerNorm: one 256-thread block per row
// ============================================================================
__global__ void ln_kernel(const float* __restrict__ x, const float* __restrict__ w,
                          const float* __restrict__ bb, float* __restrict__ y) {
    int row = blockIdx.x;
    int i   = threadIdx.x;
    float v = x[(size_t)row * DM + i];
    __shared__ float red[8];
    float s = v;
#pragma unroll
    for (int o = 16; o; o >>= 1) s += __shfl_xor_sync(0xffffffffu, s, o);
    if ((i & 31) == 0) red[i >> 5] = s;
    __syncthreads();
    float tot = 0.f;
#pragma unroll
    for (int k = 0; k < 8; k++) tot += red[k];
    float mean = tot * (1.f / DM);
    float d = v - mean;
    float s2 = d * d;
#pragma unroll
    for (int o = 16; o; o >>= 1) s2 += __shfl_xor_sync(0xffffffffu, s2, o);
    __syncthreads();
    if ((i & 31) == 0) red[i >> 5] = s2;
    __syncthreads();
    float tv = 0.f;
#pragma unroll
    for (int k = 0; k < 8; k++) tv += red[k];
    float var = tv * (1.f / DM);
    y[(size_t)row * DM + i] = d * rsqrtf(var + 1e-5f) * w[i] + bb[i];
}

// ============================================================================
// Ragged flash attention. grid = (B, NH), 256 threads.
// Tiles: Q 64xHD, K 64xHD, V 64xHD; online softmax; smem k-major for Q,K
// (KP buffer is reused: K^T during score phase, then P during PV phase).
// ============================================================================
__global__ void attn_kernel() {
    __shared__ float Qs[64 * 64]; // [k][q]
    __shared__ float KP[64 * 64]; // [k][c] then [r][j]
    __shared__ float Vs[64 * 64]; // [j][d]
    int b  = blockIdx.x, h = blockIdx.y;
    int s0 = g_start[b];
    int L  = g_start[b + 1] - s0 + 1;
    int t0 = s0 + b;
    int t  = threadIdx.x;
    int tx = t & 15, ty = t >> 4;
    int lr = t >> 2;          // 0..63
    int lc = (t & 3) * 16;    // 0,16,32,48
    const float scale = 0.125f; // 1/sqrt(64)

    for (int qc = 0; qc < L; qc += 64) {
        // load Q tile transposed
        {
            bool v = (qc + lr) < L;
            const float* qp = g_qkv + (size_t)(t0 + qc + lr) * 768 + h * HDIM + lc;
#pragma unroll
            for (int u = 0; u < 4; u++) {
                float4 q4 = v ? *(const float4*)(qp + u * 4) : make_float4(0, 0, 0, 0);
                Qs[(lc + u * 4 + 0) * 64 + lr] = q4.x;
                Qs[(lc + u * 4 + 1) * 64 + lr] = q4.y;
                Qs[(lc + u * 4 + 2) * 64 + lr] = q4.z;
                Qs[(lc + u * 4 + 3) * 64 + lr] = q4.w;
            }
        }
        float mrow[4], lrow[4], O[4][4];
#pragma unroll
        for (int i = 0; i < 4; i++) {
            mrow[i] = -1e30f; lrow[i] = 0.f;
#pragma unroll
            for (int j = 0; j < 4; j++) O[i][j] = 0.f;
        }

        for (int kc = 0; kc < L; kc += 64) {
            __syncthreads();  // prev chunk's KP/Vs reads complete; Qs stores flushed
            {
                bool v = (kc + lr) < L;
                const float* kp = g_qkv + (size_t)(t0 + kc + lr) * 768 + 256 + h * HDIM + lc;
                const float* vp = kp + 256;
#pragma unroll
                for (int u = 0; u < 4; u++) {
                    float4 k4 = v ? *(const float4*)(kp + u * 4) : make_float4(0, 0, 0, 0);
                    KP[(lc + u * 4 + 0) * 64 + lr] = k4.x;
                    KP[(lc + u * 4 + 1) * 64 + lr] = k4.y;
                    KP[(lc + u * 4 + 2) * 64 + lr] = k4.z;
                    KP[(lc + u * 4 + 3) * 64 + lr] = k4.w;
                    float4 v4 = v ? *(const float4*)(vp + u * 4) : make_float4(0, 0, 0, 0);
                    *(float4*)(Vs + lr * 64 + lc + u * 4) = v4;
                }
            }
            __syncthreads();

            float S[4][4];
#pragma unroll
            for (int i = 0; i < 4; i++)
#pragma unroll
                for (int j = 0; j < 4; j++) S[i][j] = 0.f;
#pragma unroll 8
            for (int k = 0; k < 64; k++) {
                float4 qv = *(const float4*)(Qs + k * 64 + ty * 4);
                float4 kv = *(const float4*)(KP + k * 64 + tx * 4);
                S[0][0] += qv.x * kv.x; S[0][1] += qv.x * kv.y; S[0][2] += qv.x * kv.z; S[0][3] += qv.x * kv.w;
                S[1][0] += qv.y * kv.x; S[1][1] += qv.y * kv.y; S[1][2] += qv.y * kv.z; S[1][3] += qv.y * kv.w;
                S[2][0] += qv.z * kv.x; S[2][1] += qv.z * kv.y; S[2][2] += qv.z * kv.z; S[2][3] += qv.z * kv.w;
                S[3][0] += qv.w * kv.x; S[3][1] += qv.w * kv.y; S[3][2] += qv.w * kv.z; S[3][3] += qv.w * kv.w;
            }
            __syncthreads(); // before KP is overwritten with P

            // online softmax update (row r owned by the 16 threads with same ty)
#pragma unroll
            for (int i = 0; i < 4; i++) {
                float rm = -1e30f;
#pragma unroll
                for (int j = 0; j < 4; j++) {
                    bool valid = (kc + tx * 4 + j) < L;
                    S[i][j] = valid ? S[i][j] * scale : -1e30f;
                    rm = fmaxf(rm, S[i][j]);
                }
                rm = fmaxf(rm, __shfl_xor_sync(0xffffffffu, rm, 1));
                rm = fmaxf(rm, __shfl_xor_sync(0xffffffffu, rm, 2));
                rm = fmaxf(rm, __shfl_xor_sync(0xffffffffu, rm, 4));
                rm = fmaxf(rm, __shfl_xor_sync(0xffffffffu, rm, 8));
                float mn   = fmaxf(mrow[i], rm);
                float corr = expf(mrow[i] - mn);
                float sum  = 0.f;
#pragma unroll
                for (int j = 0; j < 4; j++) {
                    float p = expf(S[i][j] - mn);  // masked: exp(-1e30-mn) -> 0
                    sum += p;
                    KP[(ty * 4 + i) * 64 + tx * 4 + j] = p;
                }
                sum += __shfl_xor_sync(0xffffffffu, sum, 1);
                sum += __shfl_xor_sync(0xffffffffu, sum, 2);
                sum += __shfl_xor_sync(0xffffffffu, sum, 4);
                sum += __shfl_xor_sync(0xffffffffu, sum, 8);
                lrow[i] = lrow[i] * corr + sum;
                mrow[i] = mn;
#pragma unroll
                for (int j = 0; j < 4; j++) O[i][j] *= corr;
            }
            __syncthreads();

            // O += P @ V
#pragma unroll 8
            for (int j = 0; j < 64; j++) {
                float4 vv = *(const float4*)(Vs + j * 64 + tx * 4);
                float p0 = KP[(ty * 4 + 0) * 64 + j];
                float p1 = KP[(ty * 4 + 1) * 64 + j];
                float p2 = KP[(ty * 4 + 2) * 64 + j];
                float p3 = KP[(ty * 4 + 3) * 64 + j];
                O[0][0] += p0 * vv.x; O[0][1] += p0 * vv.y; O[0][2] += p0 * vv.z; O[0][3] += p0 * vv.w;
                O[1][0] += p1 * vv.x; O[1][1] += p1 * vv.y; O[1][2] += p1 * vv.z; O[1][3] += p1 * vv.w;
                O[2][0] += p2 * vv.x; O[2][1] += p2 * vv.y; O[2][2] += p2 * vv.z; O[2][3] += p2 * vv.w;
                O[3][0] += p3 * vv.x; O[3][1] += p3 * vv.y; O[3][2] += p3 * vv.z; O[3][3] += p3 * vv.w;
            }
        }

        // write out
#pragma unroll
        for (int i = 0; i < 4; i++) {
            int q = qc + ty * 4 + i;
            if (q < L) {
                float inv = 1.f / lrow[i];
                float* op = g_att + (size_t)(t0 + q) * DM + h * HDIM + tx * 4;
                op[0] = O[i][0] * inv; op[1] = O[i][1] * inv;
                op[2] = O[i][2] * inv; op[3] = O[i][3] * inv;
            }
        }
        __syncthreads();
    }
}

// ============================================================================
// head: gather CLS rows, then tiny final projection (B*2 outputs)
// ============================================================================
__global__ void gather_cls() {
    int b = blockIdx.x, d = threadIdx.x;
    g_buf[(size_t)b * DM + d] = g_tok[(size_t)(g_start[b] + b) * DM + d];
}

__global__ void head2_kernel(const float* __restrict__ hid, const float* __restrict__ w2,
                             const float* __restrict__ b2, float* __restrict__ out, int B) {
    int t = blockIdx.x * blockDim.x + threadIdx.x;
    if (t >= B * 2) return;
    int b = t >> 1, j = t & 1;
    const float* hr = hid + (size_t)b * DM;
    const float* wr = w2 + (size_t)j * DM;
    float s = 0.f;
#pragma unroll 8
    for (int k = 0; k < DM; k++) s += hr[k] * wr[k];
    out[t] = s + b2[j];
}

// ============================================================================
// launch
// ============================================================================
extern "C" void kernel_launch(void* const* d_in, const int* in_sizes, int n_in,
                              void* d_out, int out_size) {
    const float* dom_emb = (const float*)d_in[0];
    const int*   ev      = (const int*)  d_in[1];
    // d_in[2] = batch_size scalar (unused; B derived from out_size)
    const float* geom    = (const float*)d_in[3];
    const float* in_w    = (const float*)d_in[4];
    const float* in_b    = (const float*)d_in[5];
    const float* geo_w   = (const float*)d_in[6];
    const float* geo_b   = (const float*)d_in[7];
    const float* cls     = (const float*)d_in[8];
    const float* qkv_w   = (const float*)d_in[9];
    const float* qkv_b   = (const float*)d_in[10];
    const float* out_w   = (const float*)d_in[11];
    const float* out_b   = (const float*)d_in[12];
    const float* ln1w    = (const float*)d_in[13];
    const float* ln1b    = (const float*)d_in[14];
    const float* ln2w    = (const float*)d_in[15];
    const float* ln2b    = (const float*)d_in[16];
    const float* ffw1    = (const float*)d_in[17];
    const float* ffb1    = (const float*)d_in[18];
    const float* ffw2    = (const float*)d_in[19];
    const float* ffb2    = (const float*)d_in[20];
    const float* hw1     = (const float*)d_in[21];
    const float* hb1     = (const float*)d_in[22];
    const float* hw2     = (const float*)d_in[23];
    const float* hb2     = (const float*)d_in[24];
    float* out = (float*)d_out;

    int N  = in_sizes[0] / D_INP;
    int B  = out_size / 2;
    int NT = N + B;

    float *p_tok, *p_buf, *p_qkv, *p_att, *p_ff;
    cudaGetSymbolAddress((void**)&p_tok, g_tok);
    cudaGetSymbolAddress((void**)&p_buf, g_buf);
    cudaGetSymbolAddress((void**)&p_qkv, g_qkv);
    cudaGetSymbolAddress((void**)&p_att, g_att);
    cudaGetSymbolAddress((void**)&p_ff,  g_ff);

    int mgy = (NT + 63) / 64;

    // segment offsets
    starts_kernel<<<1, 256>>>(ev, N, B);
    // embedding: x = emb @ in_w^T + in_b ; pe = posenc(geom) ; x += pe @ geo_w^T + geo_b
    posenc_kernel<<<N, 256>>>(geom);
    gemm_kernel<false, false><<<dim3(DM / 64, (N + 63) / 64), 256>>>(dom_emb, in_w, in_b, p_att, N, DM, D_INP);
    gemm_kernel<false, true ><<<dim3(DM / 64, (N + 63) / 64), 256>>>(p_buf,   geo_w, geo_b, p_att, N, DM, DM);
    build_tok<<<NT, 256>>>(cls, B);

    for (int l = 0; l < NL; l++) {
        ln_kernel<<<NT, 256>>>(p_tok, ln1w + l * DM, ln1b + l * DM, p_buf);
        gemm_kernel<false, false><<<dim3(3 * DM / 64, mgy), 256>>>(
            p_buf, qkv_w + (size_t)l * 3 * DM * DM, qkv_b + (size_t)l * 3 * DM, p_qkv, NT, 3 * DM, DM);
        attn_kernel<<<dim3(B, NH), 256>>>();
        gemm_kernel<false, true ><<<dim3(DM / 64, mgy), 256>>>(
            p_att, out_w + (size_t)l * DM * DM, out_b + (size_t)l * DM, p_tok, NT, DM, DM);
        ln_kernel<<<NT, 256>>>(p_tok, ln2w + l * DM, ln2b + l * DM, p_buf);
        gemm_kernel<true,  false><<<dim3(DFF / 64, mgy), 256>>>(
            p_buf, ffw1 + (size_t)l * DFF * DM, ffb1 + (size_t)l * DFF, p_ff, NT, DFF, DM);
        gemm_kernel<false, true ><<<dim3(DM / 64, mgy), 256>>>(
            p_ff, ffw2 + (size_t)l * DM * DFF, ffb2 + (size_t)l * DM, p_tok, NT, DM, DFF);
    }

    gather_cls<<<B, 256>>>();
    gemm_kernel<true, false><<<dim3(DM / 64, (B + 63) / 64), 256>>>(p_buf, hw1, hb1, p_att, B, DM, DM);
    head2_kernel<<<1, 256>>>(p_att, hw2, hb2, out, B);
}

// round 2
// speedup vs baseline: 1.8251x; 1.8251x over previous
#include <cuda_runtime.h>
#include <math.h>
#include <stdint.h>

// ============================================================================
// EventTransformer — ragged formulation + tf32 tensor-core GEMMs.
//   token t of event b:  t==0 -> CLS, else dom (start[b] + t - 1)
//   flat token index of dom i = i + ev[i] + 1 ;  CLS of event b at start[b]+b
// ============================================================================

#define D_INP 128
#define DM    256
#define NH    4
#define HDIM  64
#define NL    4
#define DFF   1024
#define NMAXD 65536
#define BMAXD 128
#define NTMAX (NMAXD + BMAXD)

__device__ float g_tok[(size_t)NTMAX * DM];
__device__ float g_buf[(size_t)NTMAX * DM];
__device__ float g_qkv[(size_t)NTMAX * 3 * DM];
__device__ float g_att[(size_t)NTMAX * DM];
__device__ float g_ff [(size_t)NTMAX * DFF];
__device__ int   g_start[BMAXD + 1];

// ============================================================================
__global__ void starts_kernel(const int* __restrict__ ev, int N, int B) {
    int b = blockIdx.x * blockDim.x + threadIdx.x;
    if (b > B) return;
    if (b == B) { g_start[B] = N; return; }
    int lo = 0, hi = N;
    while (lo < hi) {
        int mid = (lo + hi) >> 1;
        if (ev[mid] < b) lo = mid + 1; else hi = mid;
    }
    g_start[b] = lo;
}

// ============================================================================
__global__ void posenc_kernel(const float* __restrict__ geom) {
    int i = blockIdx.x;
    int c = threadIdx.x;
    float val = 0.f;
    if (c < 252) {
        int dax  = c / 84;
        int rem  = c % 84;
        int band = rem >> 1;
        int s    = rem & 1;
        float f   = exp2f((float)band * 0.08102263646065820f); // log2(10)/41
        float ang = 6.283185307179586f * geom[i * 3 + dax] * f;
        val = s ? cosf(ang) : sinf(ang);
    }
    g_buf[(size_t)i * DM + c] = val;
}

// ============================================================================
// tf32 tensor-core GEMM: C[M,N] = (RES?C:0) + A[M,K] @ W[N,K]^T + bias, opt ReLU
// BM=128, BN=64, BK=32; 256 threads (8 warps, 4x2); warp tile 32x32;
// mma.sync m16n8k8 tf32; register-stage double buffering.
// Requires K%32==0, N%64==0. M guarded.
// ============================================================================
__device__ __forceinline__ unsigned f2tf(float x) {
    unsigned u;
    asm("cvt.rna.tf32.f32 %0, %1;" : "=r"(u) : "f"(x));
    return u;
}
__device__ __forceinline__ void mma_tf32(float c[4], const unsigned a[4], const unsigned b[2]) {
    asm volatile(
        "mma.sync.aligned.m16n8k8.row.col.f32.tf32.tf32.f32 "
        "{%0,%1,%2,%3}, {%4,%5,%6,%7}, {%8,%9}, {%0,%1,%2,%3};"
        : "+f"(c[0]), "+f"(c[1]), "+f"(c[2]), "+f"(c[3])
        : "r"(a[0]), "r"(a[1]), "r"(a[2]), "r"(a[3]), "r"(b[0]), "r"(b[1]));
}

#define SROW 36  // padded row stride (floats)

template<bool RELU, bool RES>
__global__ void __launch_bounds__(256) gemm_tf32(
        const float* __restrict__ A, const float* __restrict__ W,
        const float* __restrict__ bias, float* __restrict__ C,
        int M, int N, int K) {
    __shared__ float As[128 * SROW];
    __shared__ float Ws[64 * SROW];

    int t    = threadIdx.x;
    int wid  = t >> 5, lane = t & 31;
    int gid  = lane >> 2, tig = lane & 3;
    int wm   = (wid & 3) * 32;
    int wn   = (wid >> 2) * 32;
    int m0   = blockIdx.y * 128, n0 = blockIdx.x * 64;

    // global-load assignments
    int ar = t >> 1;            // 0..127
    int ac = (t & 1) * 16;      // 0 or 16
    int wr = t >> 2;            // 0..63
    int wc = (t & 3) * 8;       // 0,8,16,24

    const float* Ag = A + (size_t)(m0 + ar) * K + ac;
    const float* Wg = W + (size_t)(n0 + wr) * K + wc;
    bool av = (m0 + ar) < M;

    float4 arg[4], wrg[2];
    // prologue: load tile 0
#pragma unroll
    for (int u = 0; u < 4; u++)
        arg[u] = av ? *(const float4*)(Ag + u * 4) : make_float4(0, 0, 0, 0);
#pragma unroll
    for (int u = 0; u < 2; u++)
        wrg[u] = *(const float4*)(Wg + u * 4);

    float acc[2][4][4];
#pragma unroll
    for (int mi = 0; mi < 2; mi++)
#pragma unroll
        for (int ni = 0; ni < 4; ni++)
#pragma unroll
            for (int j = 0; j < 4; j++) acc[mi][ni][j] = 0.f;

    for (int k0 = 0; k0 < K; k0 += 32) {
        // store current tile (converted to tf32 bit patterns)
#pragma unroll
        for (int u = 0; u < 4; u++) {
            float4 cv;
            cv.x = __uint_as_float(f2tf(arg[u].x));
            cv.y = __uint_as_float(f2tf(arg[u].y));
            cv.z = __uint_as_float(f2tf(arg[u].z));
            cv.w = __uint_as_float(f2tf(arg[u].w));
            *(float4*)&As[ar * SROW + ac + u * 4] = cv;
        }
#pragma unroll
        for (int u = 0; u < 2; u++) {
            float4 cv;
            cv.x = __uint_as_float(f2tf(wrg[u].x));
            cv.y = __uint_as_float(f2tf(wrg[u].y));
            cv.z = __uint_as_float(f2tf(wrg[u].z));
            cv.w = __uint_as_float(f2tf(wrg[u].w));
            *(float4*)&Ws[wr * SROW + wc + u * 4] = cv;
        }
        __syncthreads();

        // prefetch next tile into registers (overlaps with compute)
        if (k0 + 32 < K) {
#pragma unroll
            for (int u = 0; u < 4; u++)
                arg[u] = av ? *(const float4*)(Ag + k0 + 32 + u * 4) : make_float4(0, 0, 0, 0);
#pragma unroll
            for (int u = 0; u < 2; u++)
                wrg[u] = *(const float4*)(Wg + k0 + 32 + u * 4);
        }

#pragma unroll
        for (int s = 0; s < 4; s++) {
            int ks = s * 8;
            unsigned a[2][4], b[4][2];
#pragma unroll
            for (int mi = 0; mi < 2; mi++) {
                int r = wm + mi * 16 + gid;
                a[mi][0] = __float_as_uint(As[r * SROW + ks + tig]);
                a[mi][1] = __float_as_uint(As[(r + 8) * SROW + ks + tig]);
                a[mi][2] = __float_as_uint(As[r * SROW + ks + tig + 4]);
                a[mi][3] = __float_as_uint(As[(r + 8) * SROW + ks + tig + 4]);
            }
#pragma unroll
            for (int ni = 0; ni < 4; ni++) {
                int rn = wn + ni * 8 + gid;
                b[ni][0] = __float_as_uint(Ws[rn * SROW + ks + tig]);
                b[ni][1] = __float_as_uint(Ws[rn * SROW + ks + tig + 4]);
            }
#pragma unroll
            for (int mi = 0; mi < 2; mi++)
#pragma unroll
                for (int ni = 0; ni < 4; ni++)
                    mma_tf32(acc[mi][ni], a[mi], b[ni]);
        }
        __syncthreads();
    }

    // epilogue
#pragma unroll
    for (int mi = 0; mi < 2; mi++) {
#pragma unroll
        for (int ni = 0; ni < 4; ni++) {
            int r  = m0 + wm + mi * 16 + gid;
            int cn = n0 + wn + ni * 8 + 2 * tig;
            float b0 = bias[cn], b1 = bias[cn + 1];
            if (r < M) {
                float v0 = acc[mi][ni][0] + b0;
                float v1 = acc[mi][ni][1] + b1;
                float* cp = C + (size_t)r * N + cn;
                if (RES) { v0 += cp[0]; v1 += cp[1]; }
                if (RELU) { v0 = fmaxf(v0, 0.f); v1 = fmaxf(v1, 0.f); }
                cp[0] = v0; cp[1] = v1;
            }
            if (r + 8 < M) {
                float v0 = acc[mi][ni][2] + b0;
                float v1 = acc[mi][ni][3] + b1;
                float* cp = C + (size_t)(r + 8) * N + cn;
                if (RES) { v0 += cp[0]; v1 += cp[1]; }
                if (RELU) { v0 = fmaxf(v0, 0.f); v1 = fmaxf(v1, 0.f); }
                cp[0] = v0; cp[1] = v1;
            }
        }
    }
}

// ============================================================================
__global__ void build_tok(const float* __restrict__ cls, int B) {
    int tk = blockIdx.x;
    __shared__ int sb;
    if (threadIdx.x == 0) {
        int lo = 0, hi = B - 1;
        while (lo < hi) {
            int mid = (lo + hi + 1) >> 1;
            if (g_start[mid] + mid <= tk) lo = mid; else hi = mid - 1;
        }
        sb = lo;
    }
    __syncthreads();
    int b = sb;
    int d = threadIdx.x;
    float v;
    if (tk == g_start[b] + b) v = cls[d];
    else                      v = g_att[(size_t)(tk - b - 1) * DM + d];
    g_tok[(size_t)tk * DM + d] = v;
}

// ============================================================================
__global__ void ln_kernel(const float* __restrict__ x, const float* __restrict__ w,
                          const float* __restrict__ bb, float* __restrict__ y) {
    int row = blockIdx.x;
    int i   = threadIdx.x;
    float v = x[(size_t)row * DM + i];
    __shared__ float red[8];
    float s = v;
#pragma unroll
    for (int o = 16; o; o >>= 1) s += __shfl_xor_sync(0xffffffffu, s, o);
    if ((i & 31) == 0) red[i >> 5] = s;
    __syncthreads();
    float tot = 0.f;
#pragma unroll
    for (int k = 0; k < 8; k++) tot += red[k];
    float mean = tot * (1.f / DM);
    float d = v - mean;
    float s2 = d * d;
#pragma unroll
    for (int o = 16; o; o >>= 1) s2 += __shfl_xor_sync(0xffffffffu, s2, o);
    __syncthreads();
    if ((i & 31) == 0) red[i >> 5] = s2;
    __syncthreads();
    float tv = 0.f;
#pragma unroll
    for (int k = 0; k < 8; k++) tv += red[k];
    float var = tv * (1.f / DM);
    y[(size_t)row * DM + i] = d * rsqrtf(var + 1e-5f) * w[i] + bb[i];
}

// ============================================================================
// Ragged flash attention. grid = (B, NH, MAXQC); each block owns ONE 64-row
// Q chunk (early exit if past end) and sweeps K chunks. fp32 SIMT math.
// ============================================================================
#define MAXQC 12

__global__ void attn_kernel() {
    __shared__ float Qs[64 * 64]; // [k][q]
    __shared__ float KP[64 * 64]; // [k][c] then [r][j]
    __shared__ float Vs[64 * 64]; // [j][d]
    int b  = blockIdx.x, h = blockIdx.y;
    int s0 = g_start[b];
    int L  = g_start[b + 1] - s0 + 1;
    int qc = blockIdx.z * 64;
    if (qc >= L) return;
    int t0 = s0 + b;
    int t  = threadIdx.x;
    int tx = t & 15, ty = t >> 4;
    int lr = t >> 2;          // 0..63
    int lc = (t & 3) * 16;    // 0,16,32,48
    const float scale = 0.125f; // 1/sqrt(64)

    // load Q tile transposed
    {
        bool v = (qc + lr) < L;
        const float* qp = g_qkv + (size_t)(t0 + qc + lr) * 768 + h * HDIM + lc;
#pragma unroll
        for (int u = 0; u < 4; u++) {
            float4 q4 = v ? *(const float4*)(qp + u * 4) : make_float4(0, 0, 0, 0);
            Qs[(lc + u * 4 + 0) * 64 + lr] = q4.x;
            Qs[(lc + u * 4 + 1) * 64 + lr] = q4.y;
            Qs[(lc + u * 4 + 2) * 64 + lr] = q4.z;
            Qs[(lc + u * 4 + 3) * 64 + lr] = q4.w;
        }
    }
    float mrow[4], lrow[4], O[4][4];
#pragma unroll
    for (int i = 0; i < 4; i++) {
        mrow[i] = -1e30f; lrow[i] = 0.f;
#pragma unroll
        for (int j = 0; j < 4; j++) O[i][j] = 0.f;
    }

    for (int kc = 0; kc < L; kc += 64) {
        __syncthreads();
        {
            bool v = (kc + lr) < L;
            const float* kp = g_qkv + (size_t)(t0 + kc + lr) * 768 + 256 + h * HDIM + lc;
            const float* vp = kp + 256;
#pragma unroll
            for (int u = 0; u < 4; u++) {
                float4 k4 = v ? *(const float4*)(kp + u * 4) : make_float4(0, 0, 0, 0);
                KP[(lc + u * 4 + 0) * 64 + lr] = k4.x;
                KP[(lc + u * 4 + 1) * 64 + lr] = k4.y;
                KP[(lc + u * 4 + 2) * 64 + lr] = k4.z;
                KP[(lc + u * 4 + 3) * 64 + lr] = k4.w;
                float4 v4 = v ? *(const float4*)(vp + u * 4) : make_float4(0, 0, 0, 0);
                *(float4*)(Vs + lr * 64 + lc + u * 4) = v4;
            }
        }
        __syncthreads();

        float S[4][4];
#pragma unroll
        for (int i = 0; i < 4; i++)
#pragma unroll
            for (int j = 0; j < 4; j++) S[i][j] = 0.f;
#pragma unroll 8
        for (int k = 0; k < 64; k++) {
            float4 qv = *(const float4*)(Qs + k * 64 + ty * 4);
            float4 kv = *(const float4*)(KP + k * 64 + tx * 4);
            S[0][0] += qv.x * kv.x; S[0][1] += qv.x * kv.y; S[0][2] += qv.x * kv.z; S[0][3] += qv.x * kv.w;
            S[1][0] += qv.y * kv.x; S[1][1] += qv.y * kv.y; S[1][2] += qv.y * kv.z; S[1][3] += qv.y * kv.w;
            S[2][0] += qv.z * kv.x; S[2][1] += qv.z * kv.y; S[2][2] += qv.z * kv.z; S[2][3] += qv.z * kv.w;
            S[3][0] += qv.w * kv.x; S[3][1] += qv.w * kv.y; S[3][2] += qv.w * kv.z; S[3][3] += qv.w * kv.w;
        }
        __syncthreads(); // before KP is overwritten with P

#pragma unroll
        for (int i = 0; i < 4; i++) {
            float rm = -1e30f;
#pragma unroll
            for (int j = 0; j < 4; j++) {
                bool valid = (kc + tx * 4 + j) < L;
                S[i][j] = valid ? S[i][j] * scale : -1e30f;
                rm = fmaxf(rm, S[i][j]);
            }
            rm = fmaxf(rm, __shfl_xor_sync(0xffffffffu, rm, 1));
            rm = fmaxf(rm, __shfl_xor_sync(0xffffffffu, rm, 2));
            rm = fmaxf(rm, __shfl_xor_sync(0xffffffffu, rm, 4));
            rm = fmaxf(rm, __shfl_xor_sync(0xffffffffu, rm, 8));
            float mn   = fmaxf(mrow[i], rm);
            float corr = expf(mrow[i] - mn);
            float sum  = 0.f;
#pragma unroll
            for (int j = 0; j < 4; j++) {
                float p = expf(S[i][j] - mn);
                sum += p;
                KP[(ty * 4 + i) * 64 + tx * 4 + j] = p;
            }
            sum += __shfl_xor_sync(0xffffffffu, sum, 1);
            sum += __shfl_xor_sync(0xffffffffu, sum, 2);
            sum += __shfl_xor_sync(0xffffffffu, sum, 4);
            sum += __shfl_xor_sync(0xffffffffu, sum, 8);
            lrow[i] = lrow[i] * corr + sum;
            mrow[i] = mn;
#pragma unroll
            for (int j = 0; j < 4; j++) O[i][j] *= corr;
        }
        __syncthreads();

#pragma unroll 8
        for (int j = 0; j < 64; j++) {
            float4 vv = *(const float4*)(Vs + j * 64 + tx * 4);
            float p0 = KP[(ty * 4 + 0) * 64 + j];
            float p1 = KP[(ty * 4 + 1) * 64 + j];
            float p2 = KP[(ty * 4 + 2) * 64 + j];
            float p3 = KP[(ty * 4 + 3) * 64 + j];
            O[0][0] += p0 * vv.x; O[0][1] += p0 * vv.y; O[0][2] += p0 * vv.z; O[0][3] += p0 * vv.w;
            O[1][0] += p1 * vv.x; O[1][1] += p1 * vv.y; O[1][2] += p1 * vv.z; O[1][3] += p1 * vv.w;
            O[2][0] += p2 * vv.x; O[2][1] += p2 * vv.y; O[2][2] += p2 * vv.z; O[2][3] += p2 * vv.w;
            O[3][0] += p3 * vv.x; O[3][1] += p3 * vv.y; O[3][2] += p3 * vv.z; O[3][3] += p3 * vv.w;
        }
    }

#pragma unroll
    for (int i = 0; i < 4; i++) {
        int q = qc + ty * 4 + i;
        if (q < L) {
            float inv = 1.f / lrow[i];
            float* op = g_att + (size_t)(t0 + q) * DM + h * HDIM + tx * 4;
            op[0] = O[i][0] * inv; op[1] = O[i][1] * inv;
            op[2] = O[i][2] * inv; op[3] = O[i][3] * inv;
        }
    }
}

// ============================================================================
__global__ void gather_cls() {
    int b = blockIdx.x, d = threadIdx.x;
    g_buf[(size_t)b * DM + d] = g_tok[(size_t)(g_start[b] + b) * DM + d];
}

__global__ void head2_kernel(const float* __restrict__ hid, const float* __restrict__ w2,
                             const float* __restrict__ b2, float* __restrict__ out, int B) {
    int t = blockIdx.x * blockDim.x + threadIdx.x;
    if (t >= B * 2) return;
    int b = t >> 1, j = t & 1;
    const float* hr = hid + (size_t)b * DM;
    const float* wr = w2 + (size_t)j * DM;
    float s = 0.f;
#pragma unroll 8
    for (int k = 0; k < DM; k++) s += hr[k] * wr[k];
    out[t] = s + b2[j];
}

// ============================================================================
extern "C" void kernel_launch(void* const* d_in, const int* in_sizes, int n_in,
                              void* d_out, int out_size) {
    const float* dom_emb = (const float*)d_in[0];
    const int*   ev      = (const int*)  d_in[1];
    const float* geom    = (const float*)d_in[3];
    const float* in_w    = (const float*)d_in[4];
    const float* in_b    = (const float*)d_in[5];
    const float* geo_w   = (const float*)d_in[6];
    const float* geo_b   = (const float*)d_in[7];
    const float* cls     = (const float*)d_in[8];
    const float* qkv_w   = (const float*)d_in[9];
    const float* qkv_b   = (const float*)d_in[10];
    const float* out_w   = (const float*)d_in[11];
    const float* out_b   = (const float*)d_in[12];
    const float* ln1w    = (const float*)d_in[13];
    const float* ln1b    = (const float*)d_in[14];
    const float* ln2w    = (const float*)d_in[15];
    const float* ln2b    = (const float*)d_in[16];
    const float* ffw1    = (const float*)d_in[17];
    const float* ffb1    = (const float*)d_in[18];
    const float* ffw2    = (const float*)d_in[19];
    const float* ffb2    = (const float*)d_in[20];
    const float* hw1     = (const float*)d_in[21];
    const float* hb1     = (const float*)d_in[22];
    const float* hw2     = (const float*)d_in[23];
    const float* hb2     = (const float*)d_in[24];
    float* out = (float*)d_out;

    int N  = in_sizes[0] / D_INP;
    int B  = out_size / 2;
    int NT = N + B;

    float *p_tok, *p_buf, *p_qkv, *p_att, *p_ff;
    cudaGetSymbolAddress((void**)&p_tok, g_tok);
    cudaGetSymbolAddress((void**)&p_buf, g_buf);
    cudaGetSymbolAddress((void**)&p_qkv, g_qkv);
    cudaGetSymbolAddress((void**)&p_att, g_att);
    cudaGetSymbolAddress((void**)&p_ff,  g_ff);

    int mg  = (NT + 127) / 128;
    int mgN = (N + 127) / 128;

    starts_kernel<<<1, 256>>>(ev, N, B);
    posenc_kernel<<<N, 256>>>(geom);
    gemm_tf32<false, false><<<dim3(DM / 64, mgN), 256>>>(dom_emb, in_w, in_b, p_att, N, DM, D_INP);
    gemm_tf32<false, true ><<<dim3(DM / 64, mgN), 256>>>(p_buf,   geo_w, geo_b, p_att, N, DM, DM);
    build_tok<<<NT, 256>>>(cls, B);

    for (int l = 0; l < NL; l++) {
        ln_kernel<<<NT, 256>>>(p_tok, ln1w + l * DM, ln1b + l * DM, p_buf);
        gemm_tf32<false, false><<<dim3(3 * DM / 64, mg), 256>>>(
            p_buf, qkv_w + (size_t)l * 3 * DM * DM, qkv_b + (size_t)l * 3 * DM, p_qkv, NT, 3 * DM, DM);
        attn_kernel<<<dim3(B, NH, MAXQC), 256>>>();
        gemm_tf32<false, true ><<<dim3(DM / 64, mg), 256>>>(
            p_att, out_w + (size_t)l * DM * DM, out_b + (size_t)l * DM, p_tok, NT, DM, DM);
        ln_kernel<<<NT, 256>>>(p_tok, ln2w + l * DM, ln2b + l * DM, p_buf);
        gemm_tf32<true,  false><<<dim3(DFF / 64, mg), 256>>>(
            p_buf, ffw1 + (size_t)l * DFF * DM, ffb1 + (size_t)l * DFF, p_ff, NT, DFF, DM);
        gemm_tf32<false, true ><<<dim3(DM / 64, mg), 256>>>(
            p_ff, ffw2 + (size_t)l * DM * DFF, ffb2 + (size_t)l * DM, p_tok, NT, DM, DFF);
    }

    gather_cls<<<B, 256>>>();
    gemm_tf32<true, false><<<dim3(DM / 64, (B + 127) / 128), 256>>>(p_buf, hw1, hb1, p_att, B, DM, DM);
    head2_kernel<<<1, 256>>>(p_att, hw2, hb2, out, B);
}

// round 4
// speedup vs baseline: 2.2183x; 1.2154x over previous
#include <cuda_runtime.h>
#include <math.h>
#include <stdint.h>

// ============================================================================
// EventTransformer — ragged formulation; tf32 mma.sync GEMMs (sm_100 baseline
// ISA: no tcgen05 on this build target); fp32 SIMT ragged flash attention.
// ============================================================================

#define D_INP 128
#define DM    256
#define NH    4
#define HDIM  64
#define NL    4
#define DFF   1024
#define NMAXD 65536
#define BMAXD 128
#define NTMAX (NMAXD + BMAXD)

__device__ float g_tok[(size_t)NTMAX * DM];
__device__ float g_buf[(size_t)NTMAX * DM];
__device__ float g_qkv[(size_t)NTMAX * 3 * DM];
__device__ float g_att[(size_t)NTMAX * DM];
__device__ float g_ff [(size_t)NTMAX * DFF];
__device__ int   g_start[BMAXD + 1];

// ---------------------------------------------------------------------------
__device__ __forceinline__ uint32_t smem_u32(const void* p) {
    uint32_t a;
    asm("{ .reg .u64 t; cvta.to.shared.u64 t, %1; cvt.u32.u64 %0, t; }" : "=r"(a) : "l"(p));
    return a;
}
__device__ __forceinline__ unsigned f2tf(float x) {
    unsigned u;
    asm("cvt.rna.tf32.f32 %0, %1;" : "=r"(u) : "f"(x));
    return u;
}
__device__ __forceinline__ void mma_tf32(float c[4], const unsigned a[4], const unsigned b[2]) {
    asm volatile(
        "mma.sync.aligned.m16n8k8.row.col.f32.tf32.tf32.f32 "
        "{%0,%1,%2,%3}, {%4,%5,%6,%7}, {%8,%9}, {%0,%1,%2,%3};"
        : "+f"(c[0]), "+f"(c[1]), "+f"(c[2]), "+f"(c[3])
        : "r"(a[0]), "r"(a[1]), "r"(a[2]), "r"(a[3]), "r"(b[0]), "r"(b[1]));
}
#define CPA16(dst, src, sz) \
    asm volatile("cp.async.cg.shared.global [%0], [%1], 16, %2;" \
                 :: "r"(dst), "l"(src), "r"(sz) : "memory")
#define CPA_COMMIT() asm volatile("cp.async.commit_group;" ::: "memory")
#define CPA_WAIT1()  asm volatile("cp.async.wait_group 1;" ::: "memory")

// ---------------------------------------------------------------------------
__global__ void starts_kernel(const int* __restrict__ ev, int N, int B) {
    int b = blockIdx.x * blockDim.x + threadIdx.x;
    if (b > B) return;
    if (b == B) { g_start[B] = N; return; }
    int lo = 0, hi = N;
    while (lo < hi) {
        int mid = (lo + hi) >> 1;
        if (ev[mid] < b) lo = mid + 1; else hi = mid;
    }
    g_start[b] = lo;
}

__global__ void posenc_kernel(const float* __restrict__ geom) {
    int i = blockIdx.x;
    int c = threadIdx.x;
    float val = 0.f;
    if (c < 252) {
        int dax  = c / 84;
        int rem  = c % 84;
        int band = rem >> 1;
        int s    = rem & 1;
        float f   = exp2f((float)band * 0.08102263646065820f); // log2(10)/41
        float ang = 6.283185307179586f * geom[i * 3 + dax] * f;
        val = s ? cosf(ang) : sinf(ang);
    }
    g_buf[(size_t)i * DM + c] = val;
}

// ---------------------------------------------------------------------------
// tf32 GEMM v3: C[M,N] = (RES?C:0) + A[M,K] @ W[N,K]^T + bias[N], opt ReLU.
// BM=128, BN=128, BK=32. 256 threads = 8 warps, warp tile 64x32 (2x4 grid).
// cp.async 2-stage pipeline; padded smem (stride 36 floats, conflict-free);
// cvt.rna on fragment load; mma.sync m16n8k8. Requires N%128==0, K%32==0.
// ---------------------------------------------------------------------------
#define GSTRIDE 36
#define GTILE   (128 * GSTRIDE)            // floats per operand tile
#define GSTAGEF (2 * GTILE)                // floats per stage (A + B)
#define GSMEM   (2 * GSTAGEF * 4)          // bytes, 2 stages

template<bool RELU, bool RES>
__global__ void __launch_bounds__(256, 2) gemm3(
        const float* __restrict__ A, const float* __restrict__ W,
        const float* __restrict__ bias, float* __restrict__ C,
        int M, int N, int K) {
    extern __shared__ float sm[];
    const uint32_t sb = smem_u32(sm);

    const int t = threadIdx.x;
    const int lane = t & 31, gid = lane >> 2, tig = lane & 3;
    const int wid = t >> 5;
    const int wm = (wid & 1) * 64;
    const int wn = (wid >> 1) * 32;
    const int m0 = blockIdx.y * 128, n0 = blockIdx.x * 128;
    const int nc = K >> 5;

    // loader: 4 x 16B for A + 4 x 16B for W per thread per chunk
    const int lr = t >> 1;               // base pattern: u = i*256 + t
    auto load_chunk = [&](int c, int s) {
        int k0 = c * 32;
        uint32_t abase = sb + (s * GSTAGEF) * 4;
        uint32_t wbase = abase + GTILE * 4;
#pragma unroll
        for (int i = 0; i < 4; i++) {
            int u = i * 256 + t;
            int r = u >> 3, q = u & 7;       // r 0..127, q 0..7 (16B chunk)
            int ma  = m0 + r;
            int mac = ma < M ? ma : (M - 1);
            uint32_t sz = ma < M ? 16u : 0u;
            uint32_t da = abase + (r * GSTRIDE + q * 4) * 4;
            CPA16(da, A + (size_t)mac * K + k0 + q * 4, sz);
            uint32_t dw = wbase + (r * GSTRIDE + q * 4) * 4;
            CPA16(dw, W + (size_t)(n0 + r) * K + k0 + q * 4, 16u);
        }
    };

    load_chunk(0, 0); CPA_COMMIT();
    if (nc > 1) load_chunk(1, 1);
    CPA_COMMIT();

    float acc[4][4][4];
#pragma unroll
    for (int mi = 0; mi < 4; mi++)
#pragma unroll
        for (int ni = 0; ni < 4; ni++)
#pragma unroll
            for (int j = 0; j < 4; j++) acc[mi][ni][j] = 0.f;

    for (int c = 0; c < nc; c++) {
        CPA_WAIT1();
        __syncthreads();

        const float* Ab = sm + (c & 1) * GSTAGEF;
        const float* Wb = Ab + GTILE;
#pragma unroll
        for (int ks = 0; ks < 4; ks++) {
            unsigned a[4][4], b[4][2];
#pragma unroll
            for (int mi = 0; mi < 4; mi++) {
                const float* p = Ab + (wm + mi * 16 + gid) * GSTRIDE + ks * 8 + tig;
                a[mi][0] = f2tf(p[0]);
                a[mi][1] = f2tf(p[8 * GSTRIDE]);
                a[mi][2] = f2tf(p[4]);
                a[mi][3] = f2tf(p[8 * GSTRIDE + 4]);
            }
#pragma unroll
            for (int ni = 0; ni < 4; ni++) {
                const float* p = Wb + (wn + ni * 8 + gid) * GSTRIDE + ks * 8 + tig;
                b[ni][0] = f2tf(p[0]);
                b[ni][1] = f2tf(p[4]);
            }
#pragma unroll
            for (int mi = 0; mi < 4; mi++)
#pragma unroll
                for (int ni = 0; ni < 4; ni++)
                    mma_tf32(acc[mi][ni], a[mi], b[ni]);
        }
        __syncthreads();
        if (c + 2 < nc) load_chunk(c + 2, c & 1);
        CPA_COMMIT();
    }

    // epilogue
#pragma unroll
    for (int mi = 0; mi < 4; mi++) {
#pragma unroll
        for (int ni = 0; ni < 4; ni++) {
            int r  = m0 + wm + mi * 16 + gid;
            int cn = n0 + wn + ni * 8 + 2 * tig;
            float b0 = bias[cn], b1 = bias[cn + 1];
            if (r < M) {
                float v0 = acc[mi][ni][0] + b0;
                float v1 = acc[mi][ni][1] + b1;
                float* cp = C + (size_t)r * N + cn;
                if (RES) { v0 += cp[0]; v1 += cp[1]; }
                if (RELU) { v0 = fmaxf(v0, 0.f); v1 = fmaxf(v1, 0.f); }
                cp[0] = v0; cp[1] = v1;
            }
            if (r + 8 < M) {
                float v0 = acc[mi][ni][2] + b0;
                float v1 = acc[mi][ni][3] + b1;
                float* cp = C + (size_t)(r + 8) * N + cn;
                if (RES) { v0 += cp[0]; v1 += cp[1]; }
                if (RELU) { v0 = fmaxf(v0, 0.f); v1 = fmaxf(v1, 0.f); }
                cp[0] = v0; cp[1] = v1;
            }
        }
    }
}

// ---------------------------------------------------------------------------
__global__ void build_tok(const float* __restrict__ cls, int B) {
    int tk = blockIdx.x;
    __shared__ int sbv;
    if (threadIdx.x == 0) {
        int lo = 0, hi = B - 1;
        while (lo < hi) {
            int mid = (lo + hi + 1) >> 1;
            if (g_start[mid] + mid <= tk) lo = mid; else hi = mid - 1;
        }
        sbv = lo;
    }
    __syncthreads();
    int b = sbv;
    int d = threadIdx.x;
    float v;
    if (tk == g_start[b] + b) v = cls[d];
    else                      v = g_att[(size_t)(tk - b - 1) * DM + d];
    g_tok[(size_t)tk * DM + d] = v;
}

__global__ void ln_kernel(const float* __restrict__ x, const float* __restrict__ w,
                          const float* __restrict__ bb, float* __restrict__ y) {
    int row = blockIdx.x;
    int i   = threadIdx.x;
    float v = x[(size_t)row * DM + i];
    __shared__ float red[8];
    float s = v;
#pragma unroll
    for (int o = 16; o; o >>= 1) s += __shfl_xor_sync(0xffffffffu, s, o);
    if ((i & 31) == 0) red[i >> 5] = s;
    __syncthreads();
    float tot = 0.f;
#pragma unroll
    for (int k = 0; k < 8; k++) tot += red[k];
    float mean = tot * (1.f / DM);
    float d = v - mean;
    float s2 = d * d;
#pragma unroll
    for (int o = 16; o; o >>= 1) s2 += __shfl_xor_sync(0xffffffffu, s2, o);
    __syncthreads();
    if ((i & 31) == 0) red[i >> 5] = s2;
    __syncthreads();
    float tv = 0.f;
#pragma unroll
    for (int k = 0; k < 8; k++) tv += red[k];
    float var = tv * (1.f / DM);
    y[(size_t)row * DM + i] = d * rsqrtf(var + 1e-5f) * w[i] + bb[i];
}

// ---------------------------------------------------------------------------
// Ragged flash attention (fp32 SIMT). grid = (B, NH, MAXQC).
// ---------------------------------------------------------------------------
#define MAXQC 12

__global__ void attn_kernel() {
    __shared__ float Qs[64 * 64];
    __shared__ float KP[64 * 64];
    __shared__ float Vs[64 * 64];
    int b  = blockIdx.x, h = blockIdx.y;
    int s0 = g_start[b];
    int L  = g_start[b + 1] - s0 + 1;
    int qc = blockIdx.z * 64;
    if (qc >= L) return;
    int t0 = s0 + b;
    int t  = threadIdx.x;
    int tx = t & 15, ty = t >> 4;
    int lr = t >> 2;
    int lc = (t & 3) * 16;
    const float scale = 0.125f;

    {
        bool v = (qc + lr) < L;
        const float* qp = g_qkv + (size_t)(t0 + qc + lr) * 768 + h * HDIM + lc;
#pragma unroll
        for (int u = 0; u < 4; u++) {
            float4 q4 = v ? *(const float4*)(qp + u * 4) : make_float4(0, 0, 0, 0);
            Qs[(lc + u * 4 + 0) * 64 + lr] = q4.x;
            Qs[(lc + u * 4 + 1) * 64 + lr] = q4.y;
            Qs[(lc + u * 4 + 2) * 64 + lr] = q4.z;
            Qs[(lc + u * 4 + 3) * 64 + lr] = q4.w;
        }
    }
    float mrow[4], lrow[4], O[4][4];
#pragma unroll
    for (int i = 0; i < 4; i++) {
        mrow[i] = -1e30f; lrow[i] = 0.f;
#pragma unroll
        for (int j = 0; j < 4; j++) O[i][j] = 0.f;
    }

    for (int kc = 0; kc < L; kc += 64) {
        __syncthreads();
        {
            bool v = (kc + lr) < L;
            const float* kp = g_qkv + (size_t)(t0 + kc + lr) * 768 + 256 + h * HDIM + lc;
            const float* vp = kp + 256;
#pragma unroll
            for (int u = 0; u < 4; u++) {
                float4 k4 = v ? *(const float4*)(kp + u * 4) : make_float4(0, 0, 0, 0);
                KP[(lc + u * 4 + 0) * 64 + lr] = k4.x;
                KP[(lc + u * 4 + 1) * 64 + lr] = k4.y;
                KP[(lc + u * 4 + 2) * 64 + lr] = k4.z;
                KP[(lc + u * 4 + 3) * 64 + lr] = k4.w;
                float4 v4 = v ? *(const float4*)(vp + u * 4) : make_float4(0, 0, 0, 0);
                *(float4*)(Vs + lr * 64 + lc + u * 4) = v4;
            }
        }
        __syncthreads();

        float S[4][4];
#pragma unroll
        for (int i = 0; i < 4; i++)
#pragma unroll
            for (int j = 0; j < 4; j++) S[i][j] = 0.f;
#pragma unroll 8
        for (int k = 0; k < 64; k++) {
            float4 qv = *(const float4*)(Qs + k * 64 + ty * 4);
            float4 kv = *(const float4*)(KP + k * 64 + tx * 4);
            S[0][0] += qv.x * kv.x; S[0][1] += qv.x * kv.y; S[0][2] += qv.x * kv.z; S[0][3] += qv.x * kv.w;
            S[1][0] += qv.y * kv.x; S[1][1] += qv.y * kv.y; S[1][2] += qv.y * kv.z; S[1][3] += qv.y * kv.w;
            S[2][0] += qv.z * kv.x; S[2][1] += qv.z * kv.y; S[2][2] += qv.z * kv.z; S[2][3] += qv.z * kv.w;
            S[3][0] += qv.w * kv.x; S[3][1] += qv.w * kv.y; S[3][2] += qv.w * kv.z; S[3][3] += qv.w * kv.w;
        }
        __syncthreads();

#pragma unroll
        for (int i = 0; i < 4; i++) {
            float rm = -1e30f;
#pragma unroll
            for (int j = 0; j < 4; j++) {
                bool valid = (kc + tx * 4 + j) < L;
                S[i][j] = valid ? S[i][j] * scale : -1e30f;
                rm = fmaxf(rm, S[i][j]);
            }
            rm = fmaxf(rm, __shfl_xor_sync(0xffffffffu, rm, 1));
            rm = fmaxf(rm, __shfl_xor_sync(0xffffffffu, rm, 2));
            rm = fmaxf(rm, __shfl_xor_sync(0xffffffffu, rm, 4));
            rm = fmaxf(rm, __shfl_xor_sync(0xffffffffu, rm, 8));
            float mn   = fmaxf(mrow[i], rm);
            float corr = expf(mrow[i] - mn);
            float sum  = 0.f;
#pragma unroll
            for (int j = 0; j < 4; j++) {
                float p = expf(S[i][j] - mn);
                sum += p;
                KP[(ty * 4 + i) * 64 + tx * 4 + j] = p;
            }
            sum += __shfl_xor_sync(0xffffffffu, sum, 1);
            sum += __shfl_xor_sync(0xffffffffu, sum, 2);
            sum += __shfl_xor_sync(0xffffffffu, sum, 4);
            sum += __shfl_xor_sync(0xffffffffu, sum, 8);
            lrow[i] = lrow[i] * corr + sum;
            mrow[i] = mn;
#pragma unroll
            for (int j = 0; j < 4; j++) O[i][j] *= corr;
        }
        __syncthreads();

#pragma unroll 8
        for (int j = 0; j < 64; j++) {
            float4 vv = *(const float4*)(Vs + j * 64 + tx * 4);
            float p0 = KP[(ty * 4 + 0) * 64 + j];
            float p1 = KP[(ty * 4 + 1) * 64 + j];
            float p2 = KP[(ty * 4 + 2) * 64 + j];
            float p3 = KP[(ty * 4 + 3) * 64 + j];
            O[0][0] += p0 * vv.x; O[0][1] += p0 * vv.y; O[0][2] += p0 * vv.z; O[0][3] += p0 * vv.w;
            O[1][0] += p1 * vv.x; O[1][1] += p1 * vv.y; O[1][2] += p1 * vv.z; O[1][3] += p1 * vv.w;
            O[2][0] += p2 * vv.x; O[2][1] += p2 * vv.y; O[2][2] += p2 * vv.z; O[2][3] += p2 * vv.w;
            O[3][0] += p3 * vv.x; O[3][1] += p3 * vv.y; O[3][2] += p3 * vv.z; O[3][3] += p3 * vv.w;
        }
    }

#pragma unroll
    for (int i = 0; i < 4; i++) {
        int q = qc + ty * 4 + i;
        if (q < L) {
            float inv = 1.f / lrow[i];
            float* op = g_att + (size_t)(t0 + q) * DM + h * HDIM + tx * 4;
            op[0] = O[i][0] * inv; op[1] = O[i][1] * inv;
            op[2] = O[i][2] * inv; op[3] = O[i][3] * inv;
        }
    }
}

// ---------------------------------------------------------------------------
__global__ void gather_cls() {
    int b = blockIdx.x, d = threadIdx.x;
    g_buf[(size_t)b * DM + d] = g_tok[(size_t)(g_start[b] + b) * DM + d];
}

__global__ void head2_kernel(const float* __restrict__ hid, const float* __restrict__ w2,
                             const float* __restrict__ b2, float* __restrict__ out, int B) {
    int t = blockIdx.x * blockDim.x + threadIdx.x;
    if (t >= B * 2) return;
    int b = t >> 1, j = t & 1;
    const float* hr = hid + (size_t)b * DM;
    const float* wr = w2 + (size_t)j * DM;
    float s = 0.f;
#pragma unroll 8
    for (int k = 0; k < DM; k++) s += hr[k] * wr[k];
    out[t] = s + b2[j];
}

// ---------------------------------------------------------------------------
extern "C" void kernel_launch(void* const* d_in, const int* in_sizes, int n_in,
                              void* d_out, int out_size) {
    const float* dom_emb = (const float*)d_in[0];
    const int*   ev      = (const int*)  d_in[1];
    const float* geom    = (const float*)d_in[3];
    const float* in_w    = (const float*)d_in[4];
    const float* in_b    = (const float*)d_in[5];
    const float* geo_w   = (const float*)d_in[6];
    const float* geo_b   = (const float*)d_in[7];
    const float* cls     = (const float*)d_in[8];
    const float* qkv_w   = (const float*)d_in[9];
    const float* qkv_b   = (const float*)d_in[10];
    const float* out_w   = (const float*)d_in[11];
    const float* out_b   = (const float*)d_in[12];
    const float* ln1w    = (const float*)d_in[13];
    const float* ln1b    = (const float*)d_in[14];
    const float* ln2w    = (const float*)d_in[15];
    const float* ln2b    = (const float*)d_in[16];
    const float* ffw1    = (const float*)d_in[17];
    const float* ffb1    = (const float*)d_in[18];
    const float* ffw2    = (const float*)d_in[19];
    const float* ffb2    = (const float*)d_in[20];
    const float* hw1     = (const float*)d_in[21];
    const float* hb1     = (const float*)d_in[22];
    const float* hw2     = (const float*)d_in[23];
    const float* hb2     = (const float*)d_in[24];
    float* out = (float*)d_out;

    int N  = in_sizes[0] / D_INP;
    int B  = out_size / 2;
    int NT = N + B;

    float *p_tok, *p_buf, *p_qkv, *p_att, *p_ff;
    cudaGetSymbolAddress((void**)&p_tok, g_tok);
    cudaGetSymbolAddress((void**)&p_buf, g_buf);
    cudaGetSymbolAddress((void**)&p_qkv, g_qkv);
    cudaGetSymbolAddress((void**)&p_att, g_att);
    cudaGetSymbolAddress((void**)&p_ff,  g_ff);

    static bool attrs_done = false;
    if (!attrs_done) {
        cudaFuncSetAttribute(gemm3<false, false>, cudaFuncAttributeMaxDynamicSharedMemorySize, GSMEM);
        cudaFuncSetAttribute(gemm3<false, true >, cudaFuncAttributeMaxDynamicSharedMemorySize, GSMEM);
        cudaFuncSetAttribute(gemm3<true,  false>, cudaFuncAttributeMaxDynamicSharedMemorySize, GSMEM);
        attrs_done = true;
    }

    int mg  = (NT + 127) / 128;
    int mgN = (N + 127) / 128;

    starts_kernel<<<1, 256>>>(ev, N, B);
    posenc_kernel<<<N, 256>>>(geom);
    gemm3<false, false><<<dim3(DM / 128, mgN), 256, GSMEM>>>(dom_emb, in_w, in_b, p_att, N, DM, D_INP);
    gemm3<false, true ><<<dim3(DM / 128, mgN), 256, GSMEM>>>(p_buf,   geo_w, geo_b, p_att, N, DM, DM);
    build_tok<<<NT, 256>>>(cls, B);

    for (int l = 0; l < NL; l++) {
        ln_kernel<<<NT, 256>>>(p_tok, ln1w + l * DM, ln1b + l * DM, p_buf);
        gemm3<false, false><<<dim3(3 * DM / 128, mg), 256, GSMEM>>>(
            p_buf, qkv_w + (size_t)l * 3 * DM * DM, qkv_b + (size_t)l * 3 * DM, p_qkv, NT, 3 * DM, DM);
        attn_kernel<<<dim3(B, NH, MAXQC), 256>>>();
        gemm3<false, true ><<<dim3(DM / 128, mg), 256, GSMEM>>>(
            p_att, out_w + (size_t)l * DM * DM, out_b + (size_t)l * DM, p_tok, NT, DM, DM);
        ln_kernel<<<NT, 256>>>(p_tok, ln2w + l * DM, ln2b + l * DM, p_buf);
        gemm3<true,  false><<<dim3(DFF / 128, mg), 256, GSMEM>>>(
            p_buf, ffw1 + (size_t)l * DFF * DM, ffb1 + (size_t)l * DFF, p_ff, NT, DFF, DM);
        gemm3<false, true ><<<dim3(DM / 128, mg), 256, GSMEM>>>(
            p_ff, ffw2 + (size_t)l * DM * DFF, ffb2 + (size_t)l * DM, p_tok, NT, DM, DFF);
    }

    gather_cls<<<B, 256>>>();
    gemm3<true, false><<<dim3(DM / 128, (B + 127) / 128), 256, GSMEM>>>(p_buf, hw1, hb1, p_att, B, DM, DM);
    head2_kernel<<<1, 256>>>(p_att, hw2, hb2, out, B);
}

// round 5
// speedup vs baseline: 2.5403x; 1.1452x over previous
#include <cuda_runtime.h>
#include <math.h>
#include <stdint.h>

// ============================================================================
// EventTransformer — ragged formulation; tf32 mma.sync GEMMs + tf32 mma.sync
// ragged flash attention (sm_100 baseline ISA; tcgen05 unavailable here).
// ============================================================================

#define D_INP 128
#define DM    256
#define NH    4
#define HDIM  64
#define NL    4
#define DFF   1024
#define NMAXD 65536
#define BMAXD 128
#define NTMAX (NMAXD + BMAXD)

__device__ float g_tok[(size_t)NTMAX * DM];
__device__ float g_buf[(size_t)NTMAX * DM];
__device__ float g_qkv[(size_t)NTMAX * 3 * DM];
__device__ float g_att[(size_t)NTMAX * DM];
__device__ float g_ff [(size_t)NTMAX * DFF];
__device__ int   g_start[BMAXD + 1];

// ---------------------------------------------------------------------------
__device__ __forceinline__ uint32_t smem_u32(const void* p) {
    uint32_t a;
    asm("{ .reg .u64 t; cvta.to.shared.u64 t, %1; cvt.u32.u64 %0, t; }" : "=r"(a) : "l"(p));
    return a;
}
__device__ __forceinline__ unsigned f2tf(float x) {
    unsigned u;
    asm("cvt.rna.tf32.f32 %0, %1;" : "=r"(u) : "f"(x));
    return u;
}
__device__ __forceinline__ float f2tff(float x) {
    return __uint_as_float(f2tf(x));
}
__device__ __forceinline__ void mma_tf32(float c[4], const unsigned a[4], const unsigned b[2]) {
    asm volatile(
        "mma.sync.aligned.m16n8k8.row.col.f32.tf32.tf32.f32 "
        "{%0,%1,%2,%3}, {%4,%5,%6,%7}, {%8,%9}, {%0,%1,%2,%3};"
        : "+f"(c[0]), "+f"(c[1]), "+f"(c[2]), "+f"(c[3])
        : "r"(a[0]), "r"(a[1]), "r"(a[2]), "r"(a[3]), "r"(b[0]), "r"(b[1]));
}
#define CPA16(dst, src, sz) \
    asm volatile("cp.async.cg.shared.global [%0], [%1], 16, %2;" \
                 :: "r"(dst), "l"(src), "r"(sz) : "memory")
#define CPA_COMMIT() asm volatile("cp.async.commit_group;" ::: "memory")
#define CPA_WAIT1()  asm volatile("cp.async.wait_group 1;" ::: "memory")

// ---------------------------------------------------------------------------
__global__ void starts_kernel(const int* __restrict__ ev, int N, int B) {
    int b = blockIdx.x * blockDim.x + threadIdx.x;
    if (b > B) return;
    if (b == B) { g_start[B] = N; return; }
    int lo = 0, hi = N;
    while (lo < hi) {
        int mid = (lo + hi) >> 1;
        if (ev[mid] < b) lo = mid + 1; else hi = mid;
    }
    g_start[b] = lo;
}

__global__ void posenc_kernel(const float* __restrict__ geom) {
    int i = blockIdx.x;
    int c = threadIdx.x;
    float val = 0.f;
    if (c < 252) {
        int dax  = c / 84;
        int rem  = c % 84;
        int band = rem >> 1;
        int s    = rem & 1;
        float f   = exp2f((float)band * 0.08102263646065820f); // log2(10)/41
        float ang = 6.283185307179586f * geom[i * 3 + dax] * f;
        val = s ? cosf(ang) : sinf(ang);
    }
    g_buf[(size_t)i * DM + c] = val;
}

// ---------------------------------------------------------------------------
// tf32 GEMM: C[M,N] = (RES?C:0) + A[M,K] @ W[N,K]^T + bias[N], opt ReLU.
// BM=128, BN=128, BK=32. 256 threads = 8 warps, warp tile 64x32.
// ---------------------------------------------------------------------------
#define GSTRIDE 36
#define GTILE   (128 * GSTRIDE)
#define GSTAGEF (2 * GTILE)
#define GSMEM   (2 * GSTAGEF * 4)

template<bool RELU, bool RES>
__global__ void __launch_bounds__(256, 2) gemm3(
        const float* __restrict__ A, const float* __restrict__ W,
        const float* __restrict__ bias, float* __restrict__ C,
        int M, int N, int K) {
    extern __shared__ float sm[];
    const uint32_t sb = smem_u32(sm);

    const int t = threadIdx.x;
    const int lane = t & 31, gid = lane >> 2, tig = lane & 3;
    const int wid = t >> 5;
    const int wm = (wid & 1) * 64;
    const int wn = (wid >> 1) * 32;
    const int m0 = blockIdx.y * 128, n0 = blockIdx.x * 128;
    const int nc = K >> 5;

    auto load_chunk = [&](int c, int s) {
        int k0 = c * 32;
        uint32_t abase = sb + (s * GSTAGEF) * 4;
        uint32_t wbase = abase + GTILE * 4;
#pragma unroll
        for (int i = 0; i < 4; i++) {
            int u = i * 256 + t;
            int r = u >> 3, q = u & 7;
            int ma  = m0 + r;
            int mac = ma < M ? ma : (M - 1);
            uint32_t sz = ma < M ? 16u : 0u;
            uint32_t da = abase + (r * GSTRIDE + q * 4) * 4;
            CPA16(da, A + (size_t)mac * K + k0 + q * 4, sz);
            uint32_t dw = wbase + (r * GSTRIDE + q * 4) * 4;
            CPA16(dw, W + (size_t)(n0 + r) * K + k0 + q * 4, 16u);
        }
    };

    load_chunk(0, 0); CPA_COMMIT();
    if (nc > 1) load_chunk(1, 1);
    CPA_COMMIT();

    float acc[4][4][4];
#pragma unroll
    for (int mi = 0; mi < 4; mi++)
#pragma unroll
        for (int ni = 0; ni < 4; ni++)
#pragma unroll
            for (int j = 0; j < 4; j++) acc[mi][ni][j] = 0.f;

    for (int c = 0; c < nc; c++) {
        CPA_WAIT1();
        __syncthreads();

        const float* Ab = sm + (c & 1) * GSTAGEF;
        const float* Wb = Ab + GTILE;
#pragma unroll
        for (int ks = 0; ks < 4; ks++) {
            unsigned a[4][4], b[4][2];
#pragma unroll
            for (int mi = 0; mi < 4; mi++) {
                const float* p = Ab + (wm + mi * 16 + gid) * GSTRIDE + ks * 8 + tig;
                a[mi][0] = f2tf(p[0]);
                a[mi][1] = f2tf(p[8 * GSTRIDE]);
                a[mi][2] = f2tf(p[4]);
                a[mi][3] = f2tf(p[8 * GSTRIDE + 4]);
            }
#pragma unroll
            for (int ni = 0; ni < 4; ni++) {
                const float* p = Wb + (wn + ni * 8 + gid) * GSTRIDE + ks * 8 + tig;
                b[ni][0] = f2tf(p[0]);
                b[ni][1] = f2tf(p[4]);
            }
#pragma unroll
            for (int mi = 0; mi < 4; mi++)
#pragma unroll
                for (int ni = 0; ni < 4; ni++)
                    mma_tf32(acc[mi][ni], a[mi], b[ni]);
        }
        __syncthreads();
        if (c + 2 < nc) load_chunk(c + 2, c & 1);
        CPA_COMMIT();
    }

#pragma unroll
    for (int mi = 0; mi < 4; mi++) {
#pragma unroll
        for (int ni = 0; ni < 4; ni++) {
            int r  = m0 + wm + mi * 16 + gid;
            int cn = n0 + wn + ni * 8 + 2 * tig;
            float b0 = bias[cn], b1 = bias[cn + 1];
            if (r < M) {
                float v0 = acc[mi][ni][0] + b0;
                float v1 = acc[mi][ni][1] + b1;
                float* cp = C + (size_t)r * N + cn;
                if (RES) { v0 += cp[0]; v1 += cp[1]; }
                if (RELU) { v0 = fmaxf(v0, 0.f); v1 = fmaxf(v1, 0.f); }
                cp[0] = v0; cp[1] = v1;
            }
            if (r + 8 < M) {
                float v0 = acc[mi][ni][2] + b0;
                float v1 = acc[mi][ni][3] + b1;
                float* cp = C + (size_t)(r + 8) * N + cn;
                if (RES) { v0 += cp[0]; v1 += cp[1]; }
                if (RELU) { v0 = fmaxf(v0, 0.f); v1 = fmaxf(v1, 0.f); }
                cp[0] = v0; cp[1] = v1;
            }
        }
    }
}

// ---------------------------------------------------------------------------
__global__ void build_tok(const float* __restrict__ cls, int B) {
    int tk = blockIdx.x;
    __shared__ int sbv;
    if (threadIdx.x == 0) {
        int lo = 0, hi = B - 1;
        while (lo < hi) {
            int mid = (lo + hi + 1) >> 1;
            if (g_start[mid] + mid <= tk) lo = mid; else hi = mid - 1;
        }
        sbv = lo;
    }
    __syncthreads();
    int b = sbv;
    int d = threadIdx.x;
    float v;
    if (tk == g_start[b] + b) v = cls[d];
    else                      v = g_att[(size_t)(tk - b - 1) * DM + d];
    g_tok[(size_t)tk * DM + d] = v;
}

__global__ void ln_kernel(const float* __restrict__ x, const float* __restrict__ w,
                          const float* __restrict__ bb, float* __restrict__ y) {
    int row = blockIdx.x;
    int i   = threadIdx.x;
    float v = x[(size_t)row * DM + i];
    __shared__ float red[8];
    float s = v;
#pragma unroll
    for (int o = 16; o; o >>= 1) s += __shfl_xor_sync(0xffffffffu, s, o);
    if ((i & 31) == 0) red[i >> 5] = s;
    __syncthreads();
    float tot = 0.f;
#pragma unroll
    for (int k = 0; k < 8; k++) tot += red[k];
    float mean = tot * (1.f / DM);
    float d = v - mean;
    float s2 = d * d;
#pragma unroll
    for (int o = 16; o; o >>= 1) s2 += __shfl_xor_sync(0xffffffffu, s2, o);
    __syncthreads();
    if ((i & 31) == 0) red[i >> 5] = s2;
    __syncthreads();
    float tv = 0.f;
#pragma unroll
    for (int k = 0; k < 8; k++) tv += red[k];
    float var = tv * (1.f / DM);
    y[(size_t)row * DM + i] = d * rsqrtf(var + 1e-5f) * w[i] + bb[i];
}

// ---------------------------------------------------------------------------
// Ragged flash attention on tf32 mma.sync. grid = (B, NH, MAXQC), 128 threads.
// Warp w owns Q rows [qc + 16w, qc + 16w + 16). Smem (dynamic):
//   Qs[q][d] (A operand), Ks[k][d] (B operand, native layout),
//   Vt[d][k] (B operand for PV), Ps[q][j] (A operand for PV; warp-private use).
// All smem values stored pre-converted to tf32 bit patterns.
// ---------------------------------------------------------------------------
#define MAXQC 12
#define ASTR  68
#define ATT_SMEM (4 * 64 * ASTR * 4)

__global__ void __launch_bounds__(128) attn_mma() {
    extern __shared__ float asm_[];
    float* Qs = asm_;
    float* Ks = Qs + 64 * ASTR;
    float* Vt = Ks + 64 * ASTR;
    float* Ps = Vt + 64 * ASTR;

    int b  = blockIdx.x, h = blockIdx.y;
    int s0 = g_start[b];
    int L  = g_start[b + 1] - s0 + 1;
    int qc = blockIdx.z * 64;
    if (qc >= L) return;
    int t0 = s0 + b;

    int t = threadIdx.x, lane = t & 31, wid = t >> 5;
    int gid = lane >> 2, tig = lane & 3;
    int wm = wid * 16;
    int lr = t >> 1, lc = (t & 1) * 32;   // loader: row 0..63, col half

    // ---- load Q tile (converted) ----
    {
        bool v = (qc + lr) < L;
        const float* qp = g_qkv + (size_t)(t0 + qc + lr) * 768 + h * HDIM + lc;
        float* d = Qs + lr * ASTR + lc;
#pragma unroll
        for (int u = 0; u < 8; u++) {
            float4 q4 = v ? *(const float4*)(qp + u * 4) : make_float4(0, 0, 0, 0);
            d[u * 4 + 0] = f2tff(q4.x); d[u * 4 + 1] = f2tff(q4.y);
            d[u * 4 + 2] = f2tff(q4.z); d[u * 4 + 3] = f2tff(q4.w);
        }
    }

    float mr0 = -1e30f, mr1 = -1e30f, l0 = 0.f, l1 = 0.f;
    float O[8][4];
#pragma unroll
    for (int ni = 0; ni < 8; ni++)
#pragma unroll
        for (int j = 0; j < 4; j++) O[ni][j] = 0.f;

    const float scale = 0.125f;

    for (int kc = 0; kc < L; kc += 64) {
        __syncthreads();  // prior-chunk Ks/Vt reads done (also covers Qs on iter 0)
        {
            bool v = (kc + lr) < L;
            const float* kp = g_qkv + (size_t)(t0 + kc + lr) * 768 + 256 + h * HDIM + lc;
            const float* vp = kp + 256;
            float* kd = Ks + lr * ASTR + lc;
#pragma unroll
            for (int u = 0; u < 8; u++) {
                float4 k4 = v ? *(const float4*)(kp + u * 4) : make_float4(0, 0, 0, 0);
                kd[u * 4 + 0] = f2tff(k4.x); kd[u * 4 + 1] = f2tff(k4.y);
                kd[u * 4 + 2] = f2tff(k4.z); kd[u * 4 + 3] = f2tff(k4.w);
                float4 v4 = v ? *(const float4*)(vp + u * 4) : make_float4(0, 0, 0, 0);
                Vt[(lc + u * 4 + 0) * ASTR + lr] = f2tff(v4.x);
                Vt[(lc + u * 4 + 1) * ASTR + lr] = f2tff(v4.y);
                Vt[(lc + u * 4 + 2) * ASTR + lr] = f2tff(v4.z);
                Vt[(lc + u * 4 + 3) * ASTR + lr] = f2tff(v4.w);
            }
        }
        __syncthreads();

        // ---- S = Q @ K^T ----
        float S[8][4];
#pragma unroll
        for (int ni = 0; ni < 8; ni++)
#pragma unroll
            for (int j = 0; j < 4; j++) S[ni][j] = 0.f;
#pragma unroll
        for (int ks = 0; ks < 8; ks++) {
            unsigned a[4];
            const float* qb = Qs + (wm + gid) * ASTR + ks * 8 + tig;
            a[0] = __float_as_uint(qb[0]);
            a[1] = __float_as_uint(qb[8 * ASTR]);
            a[2] = __float_as_uint(qb[4]);
            a[3] = __float_as_uint(qb[8 * ASTR + 4]);
#pragma unroll
            for (int ni = 0; ni < 8; ni++) {
                unsigned bb[2];
                const float* kb = Ks + (ni * 8 + gid) * ASTR + ks * 8 + tig;
                bb[0] = __float_as_uint(kb[0]);
                bb[1] = __float_as_uint(kb[4]);
                mma_tf32(S[ni], a, bb);
            }
        }

        // ---- online softmax (rows wm+gid, wm+gid+8) ----
        float rm0 = -1e30f, rm1 = -1e30f;
#pragma unroll
        for (int ni = 0; ni < 8; ni++) {
            int j0 = kc + ni * 8 + 2 * tig;
            bool v0 = j0 < L, v1 = (j0 + 1) < L;
            S[ni][0] = v0 ? S[ni][0] * scale : -1e30f;
            S[ni][1] = v1 ? S[ni][1] * scale : -1e30f;
            S[ni][2] = v0 ? S[ni][2] * scale : -1e30f;
            S[ni][3] = v1 ? S[ni][3] * scale : -1e30f;
            rm0 = fmaxf(rm0, fmaxf(S[ni][0], S[ni][1]));
            rm1 = fmaxf(rm1, fmaxf(S[ni][2], S[ni][3]));
        }
        rm0 = fmaxf(rm0, __shfl_xor_sync(0xffffffffu, rm0, 1));
        rm0 = fmaxf(rm0, __shfl_xor_sync(0xffffffffu, rm0, 2));
        rm1 = fmaxf(rm1, __shfl_xor_sync(0xffffffffu, rm1, 1));
        rm1 = fmaxf(rm1, __shfl_xor_sync(0xffffffffu, rm1, 2));
        float mn0 = fmaxf(mr0, rm0), mn1 = fmaxf(mr1, rm1);
        float cr0 = expf(mr0 - mn0), cr1 = expf(mr1 - mn1);
        float sum0 = 0.f, sum1 = 0.f;
        float* pr0 = Ps + (wm + gid) * ASTR;
        float* pr1 = Ps + (wm + gid + 8) * ASTR;
#pragma unroll
        for (int ni = 0; ni < 8; ni++) {
            int col = ni * 8 + 2 * tig;
            float p0 = expf(S[ni][0] - mn0);
            float p1 = expf(S[ni][1] - mn0);
            float p2 = expf(S[ni][2] - mn1);
            float p3 = expf(S[ni][3] - mn1);
            sum0 += p0 + p1; sum1 += p2 + p3;
            pr0[col] = f2tff(p0); pr0[col + 1] = f2tff(p1);
            pr1[col] = f2tff(p2); pr1[col + 1] = f2tff(p3);
        }
        sum0 += __shfl_xor_sync(0xffffffffu, sum0, 1);
        sum0 += __shfl_xor_sync(0xffffffffu, sum0, 2);
        sum1 += __shfl_xor_sync(0xffffffffu, sum1, 1);
        sum1 += __shfl_xor_sync(0xffffffffu, sum1, 2);
        l0 = l0 * cr0 + sum0;
        l1 = l1 * cr1 + sum1;
        mr0 = mn0; mr1 = mn1;
#pragma unroll
        for (int ni = 0; ni < 8; ni++) {
            O[ni][0] *= cr0; O[ni][1] *= cr0;
            O[ni][2] *= cr1; O[ni][3] *= cr1;
        }
        __syncwarp();  // warp-private P round-trip

        // ---- O += P @ V ----
#pragma unroll
        for (int ks = 0; ks < 8; ks++) {
            unsigned a[4];
            const float* pb = Ps + (wm + gid) * ASTR + ks * 8 + tig;
            a[0] = __float_as_uint(pb[0]);
            a[1] = __float_as_uint(pb[8 * ASTR]);
            a[2] = __float_as_uint(pb[4]);
            a[3] = __float_as_uint(pb[8 * ASTR + 4]);
#pragma unroll
            for (int ni = 0; ni < 8; ni++) {
                unsigned bb[2];
                const float* vb = Vt + (ni * 8 + gid) * ASTR + ks * 8 + tig;
                bb[0] = __float_as_uint(vb[0]);
                bb[1] = __float_as_uint(vb[4]);
                mma_tf32(O[ni], a, bb);
            }
        }
        __syncwarp();  // P reads complete before next chunk's softmax overwrites
    }

    // ---- write out ----
    float inv0 = 1.f / l0, inv1 = 1.f / l1;
    int q0 = qc + wm + gid, q1 = q0 + 8;
#pragma unroll
    for (int ni = 0; ni < 8; ni++) {
        int col = h * HDIM + ni * 8 + 2 * tig;
        if (q0 < L) {
            float* op = g_att + (size_t)(t0 + q0) * DM + col;
            op[0] = O[ni][0] * inv0; op[1] = O[ni][1] * inv0;
        }
        if (q1 < L) {
            float* op = g_att + (size_t)(t0 + q1) * DM + col;
            op[0] = O[ni][2] * inv1; op[1] = O[ni][3] * inv1;
        }
    }
}

// ---------------------------------------------------------------------------
__global__ void gather_cls() {
    int b = blockIdx.x, d = threadIdx.x;
    g_buf[(size_t)b * DM + d] = g_tok[(size_t)(g_start[b] + b) * DM + d];
}

__global__ void head2_kernel(const float* __restrict__ hid, const float* __restrict__ w2,
                             const float* __restrict__ b2, float* __restrict__ out, int B) {
    int t = blockIdx.x * blockDim.x + threadIdx.x;
    if (t >= B * 2) return;
    int b = t >> 1, j = t & 1;
    const float* hr = hid + (size_t)b * DM;
    const float* wr = w2 + (size_t)j * DM;
    float s = 0.f;
#pragma unroll 8
    for (int k = 0; k < DM; k++) s += hr[k] * wr[k];
    out[t] = s + b2[j];
}

// ---------------------------------------------------------------------------
extern "C" void kernel_launch(void* const* d_in, const int* in_sizes, int n_in,
                              void* d_out, int out_size) {
    const float* dom_emb = (const float*)d_in[0];
    const int*   ev      = (const int*)  d_in[1];
    const float* geom    = (const float*)d_in[3];
    const float* in_w    = (const float*)d_in[4];
    const float* in_b    = (const float*)d_in[5];
    const float* geo_w   = (const float*)d_in[6];
    const float* geo_b   = (const float*)d_in[7];
    const float* cls     = (const float*)d_in[8];
    const float* qkv_w   = (const float*)d_in[9];
    const float* qkv_b   = (const float*)d_in[10];
    const float* out_w   = (const float*)d_in[11];
    const float* out_b   = (const float*)d_in[12];
    const float* ln1w    = (const float*)d_in[13];
    const float* ln1b    = (const float*)d_in[14];
    const float* ln2w    = (const float*)d_in[15];
    const float* ln2b    = (const float*)d_in[16];
    const float* ffw1    = (const float*)d_in[17];
    const float* ffb1    = (const float*)d_in[18];
    const float* ffw2    = (const float*)d_in[19];
    const float* ffb2    = (const float*)d_in[20];
    const float* hw1     = (const float*)d_in[21];
    const float* hb1     = (const float*)d_in[22];
    const float* hw2     = (const float*)d_in[23];
    const float* hb2     = (const float*)d_in[24];
    float* out = (float*)d_out;

    int N  = in_sizes[0] / D_INP;
    int B  = out_size / 2;
    int NT = N + B;

    float *p_tok, *p_buf, *p_qkv, *p_att, *p_ff;
    cudaGetSymbolAddress((void**)&p_tok, g_tok);
    cudaGetSymbolAddress((void**)&p_buf, g_buf);
    cudaGetSymbolAddress((void**)&p_qkv, g_qkv);
    cudaGetSymbolAddress((void**)&p_att, g_att);
    cudaGetSymbolAddress((void**)&p_ff,  g_ff);

    static bool attrs_done = false;
    if (!attrs_done) {
        cudaFuncSetAttribute(gemm3<false, false>, cudaFuncAttributeMaxDynamicSharedMemorySize, GSMEM);
        cudaFuncSetAttribute(gemm3<false, true >, cudaFuncAttributeMaxDynamicSharedMemorySize, GSMEM);
        cudaFuncSetAttribute(gemm3<true,  false>, cudaFuncAttributeMaxDynamicSharedMemorySize, GSMEM);
        cudaFuncSetAttribute(attn_mma, cudaFuncAttributeMaxDynamicSharedMemorySize, ATT_SMEM);
        attrs_done = true;
    }

    int mg  = (NT + 127) / 128;
    int mgN = (N + 127) / 128;

    starts_kernel<<<1, 256>>>(ev, N, B);
    posenc_kernel<<<N, 256>>>(geom);
    gemm3<false, false><<<dim3(DM / 128, mgN), 256, GSMEM>>>(dom_emb, in_w, in_b, p_att, N, DM, D_INP);
    gemm3<false, true ><<<dim3(DM / 128, mgN), 256, GSMEM>>>(p_buf,   geo_w, geo_b, p_att, N, DM, DM);
    build_tok<<<NT, 256>>>(cls, B);

    for (int l = 0; l < NL; l++) {
        ln_kernel<<<NT, 256>>>(p_tok, ln1w + l * DM, ln1b + l * DM, p_buf);
        gemm3<false, false><<<dim3(3 * DM / 128, mg), 256, GSMEM>>>(
            p_buf, qkv_w + (size_t)l * 3 * DM * DM, qkv_b + (size_t)l * 3 * DM, p_qkv, NT, 3 * DM, DM);
        attn_mma<<<dim3(B, NH, MAXQC), 128, ATT_SMEM>>>();
        gemm3<false, true ><<<dim3(DM / 128, mg), 256, GSMEM>>>(
            p_att, out_w + (size_t)l * DM * DM, out_b + (size_t)l * DM, p_tok, NT, DM, DM);
        ln_kernel<<<NT, 256>>>(p_tok, ln2w + l * DM, ln2b + l * DM, p_buf);
        gemm3<true,  false><<<dim3(DFF / 128, mg), 256, GSMEM>>>(
            p_buf, ffw1 + (size_t)l * DFF * DM, ffb1 + (size_t)l * DFF, p_ff, NT, DFF, DM);
        gemm3<false, true ><<<dim3(DM / 128, mg), 256, GSMEM>>>(
            p_ff, ffw2 + (size_t)l * DM * DFF, ffb2 + (size_t)l * DM, p_tok, NT, DM, DFF);
    }

    gather_cls<<<B, 256>>>();
    gemm3<true, false><<<dim3(DM / 128, (B + 127) / 128), 256, GSMEM>>>(p_buf, hw1, hb1, p_att, B, DM, DM);
    head2_kernel<<<1, 256>>>(p_att, hw2, hb2, out, B);
}

// round 7
// speedup vs baseline: 2.6972x; 1.0618x over previous
#include <cuda_runtime.h>
#include <math.h>
#include <stdint.h>

// ============================================================================
// EventTransformer — ragged formulation; tf32 mma.sync GEMMs with all inputs
// pre-converted to tf32 (zero cvt in hot loops); tf32 mma flash attention.
// ============================================================================

#define D_INP 128
#define DM    256
#define NH    4
#define HDIM  64
#define NL    4
#define DFF   1024
#define NMAXD 65536
#define BMAXD 128
#define NTMAX (NMAXD + BMAXD)

__device__ float g_tok[(size_t)NTMAX * DM];      // residual h (fp32)
__device__ float g_buf[(size_t)NTMAX * DM];      // LN out / posenc / cls (tf32 bits)
__device__ float g_qkv[(size_t)NTMAX * 3 * DM];  // QKV (tf32 bits)
__device__ float g_att[(size_t)NTMAX * DM];      // attn out (tf32) / embed acc (fp32)
__device__ float g_ff [(size_t)NTMAX * DFF];     // FF hidden (tf32) / embed stage
__device__ int   g_start[BMAXD + 1];

// converted weights scratch (tf32 bit patterns)
#define W_IN   0
#define W_GEO  (W_IN   + DM * D_INP)
#define W_QKV  (W_GEO  + DM * DM)
#define W_OUT  (W_QKV  + NL * 3 * DM * DM)
#define W_FF1  (W_OUT  + NL * DM * DM)
#define W_FF2  (W_FF1  + NL * DFF * DM)
#define W_HEAD (W_FF2  + NL * DM * DFF)
#define W_TOT  (W_HEAD + DM * DM)
__device__ float g_wts[W_TOT];

// ---------------------------------------------------------------------------
__device__ __forceinline__ uint32_t smem_u32(const void* p) {
    uint32_t a;
    asm("{ .reg .u64 t; cvta.to.shared.u64 t, %1; cvt.u32.u64 %0, t; }" : "=r"(a) : "l"(p));
    return a;
}
__device__ __forceinline__ unsigned f2tf(float x) {
    unsigned u;
    asm("cvt.rna.tf32.f32 %0, %1;" : "=r"(u) : "f"(x));
    return u;
}
__device__ __forceinline__ float f2tff(float x) {
    return __uint_as_float(f2tf(x));
}
__device__ __forceinline__ void mma_tf32(float c[4], const unsigned a[4], const unsigned b[2]) {
    asm volatile(
        "mma.sync.aligned.m16n8k8.row.col.f32.tf32.tf32.f32 "
        "{%0,%1,%2,%3}, {%4,%5,%6,%7}, {%8,%9}, {%0,%1,%2,%3};"
        : "+f"(c[0]), "+f"(c[1]), "+f"(c[2]), "+f"(c[3])
        : "r"(a[0]), "r"(a[1]), "r"(a[2]), "r"(a[3]), "r"(b[0]), "r"(b[1]));
}
#define CPA16(dst, src) \
    asm volatile("cp.async.cg.shared.global [%0], [%1], 16;" \
                 :: "r"(dst), "l"(src) : "memory")
#define CPA_COMMIT() asm volatile("cp.async.commit_group;" ::: "memory")
#define CPA_WAIT1()  asm volatile("cp.async.wait_group 1;" ::: "memory")

// ---------------------------------------------------------------------------
__global__ void cvt_kernel(const float* __restrict__ src, float* __restrict__ dst, int n) {
    int i = blockIdx.x * 256 + threadIdx.x;
    if (i < n) dst[i] = f2tff(src[i]);
}

__global__ void starts_kernel(const int* __restrict__ ev, int N, int B) {
    int b = blockIdx.x * blockDim.x + threadIdx.x;
    if (b > B) return;
    if (b == B) { g_start[B] = N; return; }
    int lo = 0, hi = N;
    while (lo < hi) {
        int mid = (lo + hi) >> 1;
        if (ev[mid] < b) lo = mid + 1; else hi = mid;
    }
    g_start[b] = lo;
}

__global__ void posenc_kernel(const float* __restrict__ geom) {
    int i = blockIdx.x;
    int c = threadIdx.x;
    float val = 0.f;
    if (c < 252) {
        int dax  = c / 84;
        int rem  = c % 84;
        int band = rem >> 1;
        int s    = rem & 1;
        float f   = exp2f((float)band * 0.08102263646065820f); // log2(10)/41
        float ang = 6.283185307179586f * geom[i * 3 + dax] * f;
        val = s ? cosf(ang) : sinf(ang);
    }
    g_buf[(size_t)i * DM + c] = f2tff(val);
}

// ---------------------------------------------------------------------------
// tf32 GEMM: C[M,N] = (RES?C:0) + A[M,K] @ W[N,K]^T + bias[N], opt ReLU, opt
// tf32-convert-on-store. A and W hold tf32 bit patterns. M%128==0, N%128==0,
// K%32==0 required. BM=BN=128, BK=32, 8 warps (64x32 warp tiles), 3-stage
// cp.async pipeline.
// Loop invariant (per iteration c): wait_group(1) + __syncthreads() makes
// chunk c resident AND visible to all warps (cp.async data copied by other
// threads is only visible after a barrier that FOLLOWS the wait). The load of
// chunk c+2 overwrites stage (c+2)%3 == (c-1)%3, whose last reader was
// compute(c-1) — complete for all warps by this iteration's barrier.
// Unconditional commits keep trailing empty groups so wait_group(1) stays
// sufficient at the final chunks.
// ---------------------------------------------------------------------------
#define GSTRIDE 36
#define GTILEF  (128 * GSTRIDE)       // floats per operand tile
#define GSTAGEF (2 * GTILEF)          // floats per stage
#define GSMEM   (3 * GSTAGEF * 4)     // bytes

template<bool RELU, bool RES, bool CVT>
__global__ void __launch_bounds__(256, 2) gemm3(
        const float* __restrict__ A, const float* __restrict__ W,
        const float* __restrict__ bias, float* __restrict__ C,
        int M, int N, int K) {
    extern __shared__ float sm[];
    const uint32_t sb = smem_u32(sm);

    const int t = threadIdx.x;
    const int lane = t & 31, gid = lane >> 2, tig = lane & 3;
    const int wid = t >> 5;
    const int wm = (wid & 1) * 64;
    const int wn = (wid >> 1) * 32;
    const int m0 = blockIdx.y * 128, n0 = blockIdx.x * 128;
    const int nc = K >> 5;

    auto load_chunk = [&](int c, int s) {
        int k0 = c * 32;
        uint32_t abase = sb + (s * GSTAGEF) * 4;
        uint32_t wbase = abase + GTILEF * 4;
#pragma unroll
        for (int i = 0; i < 4; i++) {
            int u = i * 256 + t;
            int r = u >> 3, q = u & 7;
            CPA16(abase + (r * GSTRIDE + q * 4) * 4, A + (size_t)(m0 + r) * K + k0 + q * 4);
            CPA16(wbase + (r * GSTRIDE + q * 4) * 4, W + (size_t)(n0 + r) * K + k0 + q * 4);
        }
    };

    load_chunk(0, 0); CPA_COMMIT();
    load_chunk(1, 1); CPA_COMMIT();   // K >= 64 always

    float acc[4][4][4];
#pragma unroll
    for (int mi = 0; mi < 4; mi++)
#pragma unroll
        for (int ni = 0; ni < 4; ni++)
#pragma unroll
            for (int j = 0; j < 4; j++) acc[mi][ni][j] = 0.f;

    for (int c = 0; c < nc; c++) {
        CPA_WAIT1();                     // chunk c's group complete (this thread)
        __syncthreads();                 // ...and visible CTA-wide

        const float* Ab = sm + (c % 3) * GSTAGEF;
        const float* Wb = Ab + GTILEF;
#pragma unroll
        for (int ks = 0; ks < 4; ks++) {
            unsigned a[4][4], b[4][2];
#pragma unroll
            for (int mi = 0; mi < 4; mi++) {
                const float* p = Ab + (wm + mi * 16 + gid) * GSTRIDE + ks * 8 + tig;
                a[mi][0] = __float_as_uint(p[0]);
                a[mi][1] = __float_as_uint(p[8 * GSTRIDE]);
                a[mi][2] = __float_as_uint(p[4]);
                a[mi][3] = __float_as_uint(p[8 * GSTRIDE + 4]);
            }
#pragma unroll
            for (int ni = 0; ni < 4; ni++) {
                const float* p = Wb + (wn + ni * 8 + gid) * GSTRIDE + ks * 8 + tig;
                b[ni][0] = __float_as_uint(p[0]);
                b[ni][1] = __float_as_uint(p[4]);
            }
#pragma unroll
            for (int mi = 0; mi < 4; mi++)
#pragma unroll
                for (int ni = 0; ni < 4; ni++)
                    mma_tf32(acc[mi][ni], a[mi], b[ni]);
        }

        if (c + 2 < nc) load_chunk(c + 2, (c + 2) % 3);
        CPA_COMMIT();                    // unconditional: keeps wait_group(1) valid
    }

#pragma unroll
    for (int mi = 0; mi < 4; mi++) {
#pragma unroll
        for (int ni = 0; ni < 4; ni++) {
            int r  = m0 + wm + mi * 16 + gid;
            int cn = n0 + wn + ni * 8 + 2 * tig;
            float b0 = bias[cn], b1 = bias[cn + 1];
            {
                float v0 = acc[mi][ni][0] + b0;
                float v1 = acc[mi][ni][1] + b1;
                float* cp = C + (size_t)r * N + cn;
                if (RES) { v0 += cp[0]; v1 += cp[1]; }
                if (RELU) { v0 = fmaxf(v0, 0.f); v1 = fmaxf(v1, 0.f); }
                if (CVT) { v0 = f2tff(v0); v1 = f2tff(v1); }
                cp[0] = v0; cp[1] = v1;
            }
            {
                float v0 = acc[mi][ni][2] + b0;
                float v1 = acc[mi][ni][3] + b1;
                float* cp = C + (size_t)(r + 8) * N + cn;
                if (RES) { v0 += cp[0]; v1 += cp[1]; }
                if (RELU) { v0 = fmaxf(v0, 0.f); v1 = fmaxf(v1, 0.f); }
                if (CVT) { v0 = f2tff(v0); v1 = f2tff(v1); }
                cp[0] = v0; cp[1] = v1;
            }
        }
    }
}

// ---------------------------------------------------------------------------
__global__ void build_tok(const float* __restrict__ cls, int B) {
    int tk = blockIdx.x;
    __shared__ int sbv;
    if (threadIdx.x == 0) {
        int lo = 0, hi = B - 1;
        while (lo < hi) {
            int mid = (lo + hi + 1) >> 1;
            if (g_start[mid] + mid <= tk) lo = mid; else hi = mid - 1;
        }
        sbv = lo;
    }
    __syncthreads();
    int b = sbv;
    int d = threadIdx.x;
    float v;
    if (tk == g_start[b] + b) v = cls[d];
    else                      v = g_att[(size_t)(tk - b - 1) * DM + d];
    g_tok[(size_t)tk * DM + d] = v;
}

// LN: reads fp32 h, writes tf32-converted output (feeds GEMM A directly)
__global__ void ln_kernel(const float* __restrict__ x, const float* __restrict__ w,
                          const float* __restrict__ bb, float* __restrict__ y) {
    int row = blockIdx.x;
    int i   = threadIdx.x;
    float v = x[(size_t)row * DM + i];
    __shared__ float red[8];
    float s = v;
#pragma unroll
    for (int o = 16; o; o >>= 1) s += __shfl_xor_sync(0xffffffffu, s, o);
    if ((i & 31) == 0) red[i >> 5] = s;
    __syncthreads();
    float tot = 0.f;
#pragma unroll
    for (int k = 0; k < 8; k++) tot += red[k];
    float mean = tot * (1.f / DM);
    float d = v - mean;
    float s2 = d * d;
#pragma unroll
    for (int o = 16; o; o >>= 1) s2 += __shfl_xor_sync(0xffffffffu, s2, o);
    __syncthreads();
    if ((i & 31) == 0) red[i >> 5] = s2;
    __syncthreads();
    float tv = 0.f;
#pragma unroll
    for (int k = 0; k < 8; k++) tv += red[k];
    float var = tv * (1.f / DM);
    y[(size_t)row * DM + i] = f2tff(d * rsqrtf(var + 1e-5f) * w[i] + bb[i]);
}

// ---------------------------------------------------------------------------
// Ragged flash attention on tf32 mma.sync. grid = (B, NH, MAXQC), 128 threads.
// g_qkv already holds tf32 bit patterns (qkv GEMM CVT store) — raw smem copies.
// Output written tf32-converted (feeds out-proj GEMM A).
// ---------------------------------------------------------------------------
#define MAXQC 12
#define ASTR  68
#define ATT_SMEM (4 * 64 * ASTR * 4)

__global__ void __launch_bounds__(128) attn_mma() {
    extern __shared__ float asm_[];
    float* Qs = asm_;
    float* Ks = Qs + 64 * ASTR;
    float* Vt = Ks + 64 * ASTR;
    float* Ps = Vt + 64 * ASTR;

    int b  = blockIdx.x, h = blockIdx.y;
    int s0 = g_start[b];
    int L  = g_start[b + 1] - s0 + 1;
    int qc = blockIdx.z * 64;
    if (qc >= L) return;
    int t0 = s0 + b;

    int t = threadIdx.x, lane = t & 31, wid = t >> 5;
    int gid = lane >> 2, tig = lane & 3;
    int wm = wid * 16;
    int lr = t >> 1, lc = (t & 1) * 32;

    {
        bool v = (qc + lr) < L;
        const float* qp = g_qkv + (size_t)(t0 + qc + lr) * 768 + h * HDIM + lc;
        float* d = Qs + lr * ASTR + lc;
#pragma unroll
        for (int u = 0; u < 8; u++) {
            float4 q4 = v ? *(const float4*)(qp + u * 4) : make_float4(0, 0, 0, 0);
            d[u * 4 + 0] = q4.x; d[u * 4 + 1] = q4.y;
            d[u * 4 + 2] = q4.z; d[u * 4 + 3] = q4.w;
        }
    }

    float mr0 = -1e30f, mr1 = -1e30f, l0 = 0.f, l1 = 0.f;
    float O[8][4];
#pragma unroll
    for (int ni = 0; ni < 8; ni++)
#pragma unroll
        for (int j = 0; j < 4; j++) O[ni][j] = 0.f;

    const float scale = 0.125f;

    for (int kc = 0; kc < L; kc += 64) {
        __syncthreads();
        {
            bool v = (kc + lr) < L;
            const float* kp = g_qkv + (size_t)(t0 + kc + lr) * 768 + 256 + h * HDIM + lc;
            const float* vp = kp + 256;
            float* kd = Ks + lr * ASTR + lc;
#pragma unroll
            for (int u = 0; u < 8; u++) {
                float4 k4 = v ? *(const float4*)(kp + u * 4) : make_float4(0, 0, 0, 0);
                kd[u * 4 + 0] = k4.x; kd[u * 4 + 1] = k4.y;
                kd[u * 4 + 2] = k4.z; kd[u * 4 + 3] = k4.w;
                float4 v4 = v ? *(const float4*)(vp + u * 4) : make_float4(0, 0, 0, 0);
                Vt[(lc + u * 4 + 0) * ASTR + lr] = v4.x;
                Vt[(lc + u * 4 + 1) * ASTR + lr] = v4.y;
                Vt[(lc + u * 4 + 2) * ASTR + lr] = v4.z;
                Vt[(lc + u * 4 + 3) * ASTR + lr] = v4.w;
            }
        }
        __syncthreads();

        float S[8][4];
#pragma unroll
        for (int ni = 0; ni < 8; ni++)
#pragma unroll
            for (int j = 0; j < 4; j++) S[ni][j] = 0.f;
#pragma unroll
        for (int ks = 0; ks < 8; ks++) {
            unsigned a[4];
            const float* qb = Qs + (wm + gid) * ASTR + ks * 8 + tig;
            a[0] = __float_as_uint(qb[0]);
            a[1] = __float_as_uint(qb[8 * ASTR]);
            a[2] = __float_as_uint(qb[4]);
            a[3] = __float_as_uint(qb[8 * ASTR + 4]);
#pragma unroll
            for (int ni = 0; ni < 8; ni++) {
                unsigned bb[2];
                const float* kb = Ks + (ni * 8 + gid) * ASTR + ks * 8 + tig;
                bb[0] = __float_as_uint(kb[0]);
                bb[1] = __float_as_uint(kb[4]);
                mma_tf32(S[ni], a, bb);
            }
        }

        float rm0 = -1e30f, rm1 = -1e30f;
#pragma unroll
        for (int ni = 0; ni < 8; ni++) {
            int j0 = kc + ni * 8 + 2 * tig;
            bool v0 = j0 < L, v1 = (j0 + 1) < L;
            S[ni][0] = v0 ? S[ni][0] * scale : -1e30f;
            S[ni][1] = v1 ? S[ni][1] * scale : -1e30f;
            S[ni][2] = v0 ? S[ni][2] * scale : -1e30f;
            S[ni][3] = v1 ? S[ni][3] * scale : -1e30f;
            rm0 = fmaxf(rm0, fmaxf(S[ni][0], S[ni][1]));
            rm1 = fmaxf(rm1, fmaxf(S[ni][2], S[ni][3]));
        }
        rm0 = fmaxf(rm0, __shfl_xor_sync(0xffffffffu, rm0, 1));
        rm0 = fmaxf(rm0, __shfl_xor_sync(0xffffffffu, rm0, 2));
        rm1 = fmaxf(rm1, __shfl_xor_sync(0xffffffffu, rm1, 1));
        rm1 = fmaxf(rm1, __shfl_xor_sync(0xffffffffu, rm1, 2));
        float mn0 = fmaxf(mr0, rm0), mn1 = fmaxf(mr1, rm1);
        float cr0 = expf(mr0 - mn0), cr1 = expf(mr1 - mn1);
        float sum0 = 0.f, sum1 = 0.f;
        float* pr0 = Ps + (wm + gid) * ASTR;
        float* pr1 = Ps + (wm + gid + 8) * ASTR;
#pragma unroll
        for (int ni = 0; ni < 8; ni++) {
            int col = ni * 8 + 2 * tig;
            float p0 = expf(S[ni][0] - mn0);
            float p1 = expf(S[ni][1] - mn0);
            float p2 = expf(S[ni][2] - mn1);
            float p3 = expf(S[ni][3] - mn1);
            sum0 += p0 + p1; sum1 += p2 + p3;
            pr0[col] = f2tff(p0); pr0[col + 1] = f2tff(p1);
            pr1[col] = f2tff(p2); pr1[col + 1] = f2tff(p3);
        }
        sum0 += __shfl_xor_sync(0xffffffffu, sum0, 1);
        sum0 += __shfl_xor_sync(0xffffffffu, sum0, 2);
        sum1 += __shfl_xor_sync(0xffffffffu, sum1, 1);
        sum1 += __shfl_xor_sync(0xffffffffu, sum1, 2);
        l0 = l0 * cr0 + sum0;
        l1 = l1 * cr1 + sum1;
        mr0 = mn0; mr1 = mn1;
#pragma unroll
        for (int ni = 0; ni < 8; ni++) {
            O[ni][0] *= cr0; O[ni][1] *= cr0;
            O[ni][2] *= cr1; O[ni][3] *= cr1;
        }
        __syncwarp();

#pragma unroll
        for (int ks = 0; ks < 8; ks++) {
            unsigned a[4];
            const float* pb = Ps + (wm + gid) * ASTR + ks * 8 + tig;
            a[0] = __float_as_uint(pb[0]);
            a[1] = __float_as_uint(pb[8 * ASTR]);
            a[2] = __float_as_uint(pb[4]);
            a[3] = __float_as_uint(pb[8 * ASTR + 4]);
#pragma unroll
            for (int ni = 0; ni < 8; ni++) {
                unsigned bb[2];
                const float* vb = Vt + (ni * 8 + gid) * ASTR + ks * 8 + tig;
                bb[0] = __float_as_uint(vb[0]);
                bb[1] = __float_as_uint(vb[4]);
                mma_tf32(O[ni], a, bb);
            }
        }
        __syncwarp();
    }

    float inv0 = 1.f / l0, inv1 = 1.f / l1;
    int q0 = qc + wm + gid, q1 = q0 + 8;
#pragma unroll
    for (int ni = 0; ni < 8; ni++) {
        int col = h * HDIM + ni * 8 + 2 * tig;
        if (q0 < L) {
            float* op = g_att + (size_t)(t0 + q0) * DM + col;
            op[0] = f2tff(O[ni][0] * inv0); op[1] = f2tff(O[ni][1] * inv0);
        }
        if (q1 < L) {
            float* op = g_att + (size_t)(t0 + q1) * DM + col;
            op[0] = f2tff(O[ni][2] * inv1); op[1] = f2tff(O[ni][3] * inv1);
        }
    }
}

// ---------------------------------------------------------------------------
__global__ void gather_cls() {
    int b = blockIdx.x, d = threadIdx.x;
    g_buf[(size_t)b * DM + d] = f2tff(g_tok[(size_t)(g_start[b] + b) * DM + d]);
}

__global__ void head2_kernel(const float* __restrict__ hid, const float* __restrict__ w2,
                             const float* __restrict__ b2, float* __restrict__ out, int B) {
    int t = blockIdx.x * blockDim.x + threadIdx.x;
    if (t >= B * 2) return;
    int b = t >> 1, j = t & 1;
    const float* hr = hid + (size_t)b * DM;
    const float* wr = w2 + (size_t)j * DM;
    float s = 0.f;
#pragma unroll 8
    for (int k = 0; k < DM; k++) s += hr[k] * wr[k];
    out[t] = s + b2[j];
}

// ---------------------------------------------------------------------------
extern "C" void kernel_launch(void* const* d_in, const int* in_sizes, int n_in,
                              void* d_out, int out_size) {
    const float* dom_emb = (const float*)d_in[0];
    const int*   ev      = (const int*)  d_in[1];
    const float* geom    = (const float*)d_in[3];
    const float* in_w    = (const float*)d_in[4];
    const float* in_b    = (const float*)d_in[5];
    const float* geo_w   = (const float*)d_in[6];
    const float* geo_b   = (const float*)d_in[7];
    const float* cls     = (const float*)d_in[8];
    const float* qkv_w   = (const float*)d_in[9];
    const float* qkv_b   = (const float*)d_in[10];
    const float* out_w   = (const float*)d_in[11];
    const float* out_b   = (const float*)d_in[12];
    const float* ln1w    = (const float*)d_in[13];
    const float* ln1b    = (const float*)d_in[14];
    const float* ln2w    = (const float*)d_in[15];
    const float* ln2b    = (const float*)d_in[16];
    const float* ffw1    = (const float*)d_in[17];
    const float* ffb1    = (const float*)d_in[18];
    const float* ffw2    = (const float*)d_in[19];
    const float* ffb2    = (const float*)d_in[20];
    const float* hw1     = (const float*)d_in[21];
    const float* hb1     = (const float*)d_in[22];
    const float* hw2     = (const float*)d_in[23];
    const float* hb2     = (const float*)d_in[24];
    float* out = (float*)d_out;

    int N  = in_sizes[0] / D_INP;
    int B  = out_size / 2;
    int NT = N + B;

    float *p_tok, *p_buf, *p_qkv, *p_att, *p_ff, *p_w;
    cudaGetSymbolAddress((void**)&p_tok, g_tok);
    cudaGetSymbolAddress((void**)&p_buf, g_buf);
    cudaGetSymbolAddress((void**)&p_qkv, g_qkv);
    cudaGetSymbolAddress((void**)&p_att, g_att);
    cudaGetSymbolAddress((void**)&p_ff,  g_ff);
    cudaGetSymbolAddress((void**)&p_w,   g_wts);

    static bool attrs_done = false;
    if (!attrs_done) {
        cudaFuncSetAttribute(gemm3<false, false, false>, cudaFuncAttributeMaxDynamicSharedMemorySize, GSMEM);
        cudaFuncSetAttribute(gemm3<false, true,  false>, cudaFuncAttributeMaxDynamicSharedMemorySize, GSMEM);
        cudaFuncSetAttribute(gemm3<false, false, true >, cudaFuncAttributeMaxDynamicSharedMemorySize, GSMEM);
        cudaFuncSetAttribute(gemm3<true,  false, true >, cudaFuncAttributeMaxDynamicSharedMemorySize, GSMEM);
        cudaFuncSetAttribute(gemm3<true,  false, false>, cudaFuncAttributeMaxDynamicSharedMemorySize, GSMEM);
        cudaFuncSetAttribute(attn_mma, cudaFuncAttributeMaxDynamicSharedMemorySize, ATT_SMEM);
        attrs_done = true;
    }

    // ---- convert weights + dom embeddings to tf32 bit patterns ----
    auto cvt = [&](const float* src, float* dst, int n) {
        cvt_kernel<<<(n + 255) / 256, 256>>>(src, dst, n);
    };
    cvt(in_w,  p_w + W_IN,   DM * D_INP);
    cvt(geo_w, p_w + W_GEO,  DM * DM);
    cvt(qkv_w, p_w + W_QKV,  NL * 3 * DM * DM);
    cvt(out_w, p_w + W_OUT,  NL * DM * DM);
    cvt(ffw1,  p_w + W_FF1,  NL * DFF * DM);
    cvt(ffw2,  p_w + W_FF2,  NL * DM * DFF);
    cvt(hw1,   p_w + W_HEAD, DM * DM);
    cvt(dom_emb, p_ff, N * D_INP);   // stage converted embeddings in g_ff

    int mg  = (NT + 127) / 128;
    int mgN = (N + 127) / 128;

    starts_kernel<<<1, 256>>>(ev, N, B);
    posenc_kernel<<<N, 256>>>(geom);
    gemm3<false, false, false><<<dim3(DM / 128, mgN), 256, GSMEM>>>(p_ff,  p_w + W_IN,  in_b,  p_att, N, DM, D_INP);
    gemm3<false, true,  false><<<dim3(DM / 128, mgN), 256, GSMEM>>>(p_buf, p_w + W_GEO, geo_b, p_att, N, DM, DM);
    build_tok<<<NT, 256>>>(cls, B);

    for (int l = 0; l < NL; l++) {
        ln_kernel<<<NT, 256>>>(p_tok, ln1w + l * DM, ln1b + l * DM, p_buf);
        gemm3<false, false, true><<<dim3(3 * DM / 128, mg), 256, GSMEM>>>(
            p_buf, p_w + W_QKV + (size_t)l * 3 * DM * DM, qkv_b + (size_t)l * 3 * DM, p_qkv, NT, 3 * DM, DM);
        attn_mma<<<dim3(B, NH, MAXQC), 128, ATT_SMEM>>>();
        gemm3<false, true, false><<<dim3(DM / 128, mg), 256, GSMEM>>>(
            p_att, p_w + W_OUT + (size_t)l * DM * DM, out_b + (size_t)l * DM, p_tok, NT, DM, DM);
        ln_kernel<<<NT, 256>>>(p_tok, ln2w + l * DM, ln2b + l * DM, p_buf);
        gemm3<true, false, true><<<dim3(DFF / 128, mg), 256, GSMEM>>>(
            p_buf, p_w + W_FF1 + (size_t)l * DFF * DM, ffb1 + (size_t)l * DFF, p_ff, NT, DFF, DM);
        gemm3<false, true, false><<<dim3(DM / 128, mg), 256, GSMEM>>>(
            p_ff, p_w + W_FF2 + (size_t)l * DM * DFF, ffb2 + (size_t)l * DM, p_tok, NT, DM, DFF);
    }

    gather_cls<<<B, 256>>>();
    gemm3<true, false, false><<<dim3(DM / 128, 1), 256, GSMEM>>>(p_buf, p_w + W_HEAD, hb1, p_att, B, DM, DM);
    head2_kernel<<<1, 256>>>(p_att, hw2, hb2, out, B);
}